// round 10
// baseline (speedup 1.0000x reference)
#include <cuda_runtime.h>
#include <cuda_fp16.h>
#include <cuda_bf16.h>

#define NN 50000
#define EE 1600000
#define ETOT (EE + NN)
#define C1 256
#define HIDV 64
#define SLOPE 0.2f

// ------------------------- scratch (static device globals) -------------------------
__device__ __align__(16) __half g_hwh[(size_t)NN * C1];    // GEMM output fp16 (gather)
__device__ __align__(16) float  g_feat[(size_t)NN * C1];   // post-BN features
__device__ __align__(16) float  g_agg[(size_t)NN * C1];    // attention aggregate
__device__ __align__(16) float  g_h3[(size_t)NN * HIDV];   // layer-3 output
__device__ __align__(16) float  g_ls[NN * 4];
__device__ __align__(16) float  g_ld[NN * 4];
__device__ int   g_deg[NN];
__device__ int   g_off[NN + 1];
__device__ int   g_cur[NN];
__device__ int   g_csr[ETOT];
__device__ int   g_bsum[256];
__device__ float g_bnsum[C1];
__device__ float g_bnsq[C1];
__device__ float g_mu[C1];
__device__ float g_rstd[C1];
__device__ float g_w2v[HIDV];
__device__ float g_cb;
__device__ float g_hs[NN];
__device__ float g_hd[NN];
// packed bf16x2 hi/lo GEMM weights (k-pair major): W1@0(16384) W2@16384(32768) W3@49152(8192)
__device__ __align__(16) unsigned g_wbh[57344];
__device__ __align__(16) unsigned g_wbl[57344];
// tf32 hi/lo for edge-MLP W1 only
__device__ __align__(16) unsigned g_whi[1024];
__device__ __align__(16) unsigned g_wlo[1024];

// ------------------------- split helpers -------------------------
__device__ __forceinline__ void split_tf32(float x, unsigned& hi, unsigned& lo) {
    unsigned h;
    asm("cvt.rna.tf32.f32 %0, %1;" : "=r"(h) : "f"(x));
    float l = x - __uint_as_float(h);
    unsigned lb;
    asm("cvt.rna.tf32.f32 %0, %1;" : "=r"(lb) : "f"(l));
    hi = h; lo = lb;
}

__device__ __forceinline__ void split2_bf16(float x0, float x1, unsigned& hw, unsigned& lw) {
    __nv_bfloat16 h0 = __float2bfloat16_rn(x0);
    __nv_bfloat16 h1 = __float2bfloat16_rn(x1);
    __nv_bfloat16 l0 = __float2bfloat16_rn(x0 - __bfloat162float(h0));
    __nv_bfloat16 l1 = __float2bfloat16_rn(x1 - __bfloat162float(h1));
    hw = ((unsigned)__bfloat16_as_ushort(h1) << 16) | (unsigned)__bfloat16_as_ushort(h0);
    lw = ((unsigned)__bfloat16_as_ushort(l1) << 16) | (unsigned)__bfloat16_as_ushort(l0);
}

__device__ __forceinline__ void mma_bf16(float* c, const unsigned* a, const unsigned* b) {
    asm volatile("mma.sync.aligned.m16n8k16.row.col.f32.bf16.bf16.f32 "
                 "{%0,%1,%2,%3}, {%4,%5,%6,%7}, {%8,%9}, {%0,%1,%2,%3};"
                 : "+f"(c[0]), "+f"(c[1]), "+f"(c[2]), "+f"(c[3])
                 : "r"(a[0]), "r"(a[1]), "r"(a[2]), "r"(a[3]),
                   "r"(b[0]), "r"(b[1]));
}

__device__ __forceinline__ void mma_tf32(float* c, const unsigned* a, const unsigned* b) {
    asm volatile("mma.sync.aligned.m16n8k8.row.col.f32.tf32.tf32.f32 "
                 "{%0,%1,%2,%3}, {%4,%5,%6,%7}, {%8,%9}, {%0,%1,%2,%3};"
                 : "+f"(c[0]), "+f"(c[1]), "+f"(c[2]), "+f"(c[3])
                 : "r"(a[0]), "r"(a[1]), "r"(a[2]), "r"(a[3]),
                   "r"(b[0]), "r"(b[1]));
}

__device__ __forceinline__ void ldsm_x4(unsigned& r0, unsigned& r1, unsigned& r2,
                                        unsigned& r3, unsigned addr) {
    asm volatile("ldmatrix.sync.aligned.m8n8.x4.shared.b16 {%0,%1,%2,%3}, [%4];"
                 : "=r"(r0), "=r"(r1), "=r"(r2), "=r"(r3) : "r"(addr));
}

// ------------------------- weight pre-split kernels -------------------------
__global__ void k_wsplit_pk(const float* __restrict__ W, int Kd, int Nc, int offset) {
    int i = blockIdx.x * blockDim.x + threadIdx.x;
    int total = (Kd >> 1) * Nc;
    if (i >= total) return;
    int kp = i / Nc, n = i - kp * Nc;
    float x0 = W[(size_t)(2 * kp) * Nc + n];
    float x1 = W[(size_t)(2 * kp + 1) * Nc + n];
    unsigned hw, lw;
    split2_bf16(x0, x1, hw, lw);
    g_wbh[offset + i] = hw;
    g_wbl[offset + i] = lw;
}

__global__ void k_wsplit(const float* __restrict__ W, int count, int offset) {
    int i = blockIdx.x * blockDim.x + threadIdx.x;
    if (i < count) {
        unsigned h, l;
        split_tf32(W[i], h, l);
        g_whi[offset + i] = h;
        g_wlo[offset + i] = l;
    }
}

// ------------------------- init / zero kernels -------------------------
__global__ void k_init() {
    int i = blockIdx.x * blockDim.x + threadIdx.x;
    if (i < NN) g_deg[i] = 1;
    for (int j = i; j < NN * 4; j += 50176) { g_ls[j] = 0.f; g_ld[j] = 0.f; }
    if (i < C1) { g_bnsum[i] = 0.f; g_bnsq[i] = 0.f; }
}

__global__ void k_zero2() {
    int i = blockIdx.x * blockDim.x + threadIdx.x;
    for (int j = i; j < NN * 4; j += 50176) { g_ls[j] = 0.f; g_ld[j] = 0.f; }
    if (i < C1) { g_bnsum[i] = 0.f; g_bnsq[i] = 0.f; }
}

// ------------------------- CSR build -------------------------
__global__ void k_hist(const int* __restrict__ ei) {
    int e = blockIdx.x * blockDim.x + threadIdx.x;
    if (e < EE) atomicAdd(&g_deg[ei[EE + e]], 1);
}

__global__ void k_scan1() {
    __shared__ int sh[256];
    int t = threadIdx.x;
    int i = blockIdx.x * 256 + t;
    int v = (i < NN) ? g_deg[i] : 0;
    sh[t] = v;
    __syncthreads();
#pragma unroll
    for (int st = 1; st < 256; st <<= 1) {
        int a = (t >= st) ? sh[t - st] : 0;
        __syncthreads();
        sh[t] += a;
        __syncthreads();
    }
    if (i < NN) g_off[i] = sh[t] - v;
    if (t == 255) g_bsum[blockIdx.x] = sh[255];
}

__global__ void k_scan2() {
    __shared__ int sh[256];
    int t = threadIdx.x;
    int v = (t < 196) ? g_bsum[t] : 0;
    sh[t] = v;
    __syncthreads();
#pragma unroll
    for (int st = 1; st < 256; st <<= 1) {
        int a = (t >= st) ? sh[t - st] : 0;
        __syncthreads();
        sh[t] += a;
        __syncthreads();
    }
    g_bsum[t] = sh[t] - v;
    if (t == 255) g_off[NN] = sh[255];
}

__global__ void k_scan3() {
    int i = blockIdx.x * blockDim.x + threadIdx.x;
    if (i < NN) {
        int o = g_off[i] + g_bsum[i >> 8];
        g_off[i] = o;
        g_cur[i] = o;
    }
}

__global__ void k_scatter(const int* __restrict__ ei) {
    int e = blockIdx.x * blockDim.x + threadIdx.x;
    if (e >= ETOT) return;
    int s, d;
    if (e < EE) { s = ei[e]; d = ei[EE + e]; }
    else        { s = e - EE; d = e - EE; }
    int pos = atomicAdd(&g_cur[d], 1);
    g_csr[pos] = s;
}

// ------------------------- BF16 split GEMM: cp.async pipeline + LDSM A-frags ----------
#define A_STR 20
#define B_STR 132
#define O_AL  10240
#define O_BH  20480
#define O_BL  28928
#define ST_SZ 37376
#define GEMM_SMEM (2 * ST_SZ)

template <int A_SRC>
__global__ __launch_bounds__(256, 2) void k_gemm_bf16(const float* __restrict__ Aparam,
                                                      const float* __restrict__ asv,
                                                      const float* __restrict__ adv,
                                                      int boff, int M, int K, int Nc, int H) {
    const float* A = (A_SRC == 0) ? Aparam : (const float*)g_feat;
    extern __shared__ char smx[];
    unsigned smBase = (unsigned)__cvta_generic_to_shared(smx);

    int t = threadIdx.x;
    int lane = t & 31;
    int wid = t >> 5;
    int warpM = (wid & 3) * 32;
    int warpN = (wid >> 2) * 64;
    int rowBase = blockIdx.y * 128;
    int colBase = blockIdx.x * 128;

    int aRow = t >> 3, aKf = t & 7;
    int bK = t >> 5, bC = (t & 31) * 4;

    // ldmatrix lane offsets: group = lane>>3
    int lmRow = ((lane >> 3) & 1) * 8 + (lane & 7);   // row within 16-row mma tile
    int lmK = (lane >> 4) * 4;                        // word offset for k8-15 tiles

    float acc[2][8][4];
#pragma unroll
    for (int mt = 0; mt < 2; mt++)
#pragma unroll
        for (int nt = 0; nt < 8; nt++)
#pragma unroll
            for (int r = 0; r < 4; r++) acc[mt][nt][r] = 0.f;

    int nCh = K >> 5;
    float4 va[4];

    auto loadA = [&](int k0) {
#pragma unroll
        for (int q = 0; q < 4; q++) {
            int gr = rowBase + aRow + 32 * q;
            va[q] = make_float4(0.f, 0.f, 0.f, 0.f);
            if (gr < M)
                va[q] = *reinterpret_cast<const float4*>(A + (size_t)gr * K + k0 + aKf * 4);
        }
    };
    auto stsA = [&](int stg) {
        unsigned* Ah = reinterpret_cast<unsigned*>(smx + stg * ST_SZ);
        unsigned* Al = reinterpret_cast<unsigned*>(smx + stg * ST_SZ + O_AL);
#pragma unroll
        for (int q = 0; q < 4; q++) {
            int row = aRow + 32 * q;
            unsigned h01, l01, h23, l23;
            split2_bf16(va[q].x, va[q].y, h01, l01);
            split2_bf16(va[q].z, va[q].w, h23, l23);
            int base = row * A_STR + aKf * 2;
            Ah[base] = h01; Ah[base + 1] = h23;
            Al[base] = l01; Al[base + 1] = l23;
        }
    };
    auto cpB = [&](int k0, int stg) {
        int kp0 = k0 >> 1;
#pragma unroll
        for (int q = 0; q < 2; q++) {
            int kk = bK + 8 * q;
            int gc = colBase + bC;
            int vbytes = (gc + 3 < Nc) ? 16 : 0;
            size_t idx = (size_t)boff + (size_t)(kp0 + kk) * Nc + (vbytes ? gc : 0);
            unsigned dH = smBase + stg * ST_SZ + O_BH + (kk * B_STR + bC) * 4;
            unsigned dL = smBase + stg * ST_SZ + O_BL + (kk * B_STR + bC) * 4;
            asm volatile("cp.async.cg.shared.global [%0], [%1], 16, %2;"
                         :: "r"(dH), "l"(g_wbh + idx), "r"(vbytes));
            asm volatile("cp.async.cg.shared.global [%0], [%1], 16, %2;"
                         :: "r"(dL), "l"(g_wbl + idx), "r"(vbytes));
        }
    };

    loadA(0);
    cpB(0, 0);
    asm volatile("cp.async.commit_group;" ::: "memory");
    stsA(0);

    int buf = 0;
    for (int c = 0; c < nCh; c++) {
        asm volatile("cp.async.wait_group 0;" ::: "memory");
        __syncthreads();
        if (c + 1 < nCh) {
            loadA((c + 1) * 32);
            cpB((c + 1) * 32, buf ^ 1);
            asm volatile("cp.async.commit_group;" ::: "memory");
        }
        {
            unsigned aBaseH = smBase + buf * ST_SZ;
            unsigned aBaseL = aBaseH + O_AL;
            unsigned* Bh = reinterpret_cast<unsigned*>(smx + buf * ST_SZ + O_BH);
            unsigned* Bl = reinterpret_cast<unsigned*>(smx + buf * ST_SZ + O_BL);
            int kq = lane & 3;
#pragma unroll
            for (int s = 0; s < 2; s++) {
                unsigned ahi[2][4], alo[2][4];
#pragma unroll
                for (int mt = 0; mt < 2; mt++) {
                    unsigned off = ((warpM + mt * 16 + lmRow) * A_STR + s * 8 + lmK) * 4;
                    ldsm_x4(ahi[mt][0], ahi[mt][1], ahi[mt][2], ahi[mt][3], aBaseH + off);
                    ldsm_x4(alo[mt][0], alo[mt][1], alo[mt][2], alo[mt][3], aBaseL + off);
                }
#pragma unroll
                for (int nt = 0; nt < 8; nt++) {
                    int bn = warpN + nt * 8 + (lane >> 2);
                    unsigned bhi[2], blo[2];
                    bhi[0] = Bh[(s * 8 + kq) * B_STR + bn];
                    bhi[1] = Bh[(s * 8 + kq + 4) * B_STR + bn];
                    blo[0] = Bl[(s * 8 + kq) * B_STR + bn];
                    blo[1] = Bl[(s * 8 + kq + 4) * B_STR + bn];
#pragma unroll
                    for (int mt = 0; mt < 2; mt++) {
                        mma_bf16(acc[mt][nt], ahi[mt], bhi);
                        mma_bf16(acc[mt][nt], alo[mt], bhi);
                        mma_bf16(acc[mt][nt], ahi[mt], blo);
                    }
                }
            }
        }
        if (c + 1 < nCh) stsA(buf ^ 1);
        buf ^= 1;
    }

    // epilogue: fp16 store + fused ls/ld
#pragma unroll
    for (int mt = 0; mt < 2; mt++) {
#pragma unroll
        for (int nt = 0; nt < 8; nt++) {
            int row0 = rowBase + warpM + mt * 16 + (lane >> 2);
            int col0 = colBase + warpN + nt * 8 + (lane & 3) * 2;
            if (col0 < Nc) {
                if (row0 < M)
                    *reinterpret_cast<__half2*>(g_hwh + (size_t)row0 * Nc + col0) =
                        __floats2half2_rn(acc[mt][nt][0], acc[mt][nt][1]);
                if (row0 + 8 < M)
                    *reinterpret_cast<__half2*>(g_hwh + (size_t)(row0 + 8) * Nc + col0) =
                        __floats2half2_rn(acc[mt][nt][2], acc[mt][nt][3]);
            }
        }
    }

    if (warpN < Nc) {
        int head = (colBase + warpN) >> 6;
        float pls[2][2] = {{0.f, 0.f}, {0.f, 0.f}};
        float pld[2][2] = {{0.f, 0.f}, {0.f, 0.f}};
#pragma unroll
        for (int nt = 0; nt < 8; nt++) {
            int c0 = colBase + warpN + nt * 8 + (lane & 3) * 2;
            float2 ws = *reinterpret_cast<const float2*>(asv + c0);
            float2 wd = *reinterpret_cast<const float2*>(adv + c0);
#pragma unroll
            for (int mt = 0; mt < 2; mt++) {
                pls[mt][0] += acc[mt][nt][0] * ws.x + acc[mt][nt][1] * ws.y;
                pls[mt][1] += acc[mt][nt][2] * ws.x + acc[mt][nt][3] * ws.y;
                pld[mt][0] += acc[mt][nt][0] * wd.x + acc[mt][nt][1] * wd.y;
                pld[mt][1] += acc[mt][nt][2] * wd.x + acc[mt][nt][3] * wd.y;
            }
        }
#pragma unroll
        for (int mt = 0; mt < 2; mt++)
#pragma unroll
            for (int rr = 0; rr < 2; rr++) {
                pls[mt][rr] += __shfl_xor_sync(0xffffffffu, pls[mt][rr], 1);
                pls[mt][rr] += __shfl_xor_sync(0xffffffffu, pls[mt][rr], 2);
                pld[mt][rr] += __shfl_xor_sync(0xffffffffu, pld[mt][rr], 1);
                pld[mt][rr] += __shfl_xor_sync(0xffffffffu, pld[mt][rr], 2);
            }
        if ((lane & 3) == 0) {
#pragma unroll
            for (int mt = 0; mt < 2; mt++)
#pragma unroll
                for (int rr = 0; rr < 2; rr++) {
                    int row = rowBase + warpM + mt * 16 + (lane >> 2) + rr * 8;
                    if (row < M) {
                        atomicAdd(&g_ls[row * H + head], pls[mt][rr]);
                        atomicAdd(&g_ld[row * H + head], pld[mt][rr]);
                    }
                }
        }
    }
}

// ------------------------- GAT aggregate: warp/dst, depth-1 software pipeline ---------
template <int H, int DSTSEL>
__global__ void k_aggregate(const float* __restrict__ bias) {
    float* out = (DSTSEL == 0) ? (float*)g_agg : (float*)g_h3;
    int w = (blockIdx.x * blockDim.x + threadIdx.x) >> 5;
    int lane = threadIdx.x & 31;
    if (w >= NN) return;
    int beg = g_off[w], end = g_off[w + 1];

    if (H == 4) {
        float4 ldv = *reinterpret_cast<const float4*>(g_ld + w * 4);
        float s0 = 0.f, s1 = 0.f, s2 = 0.f, s3 = 0.f;
        float a0 = 0.f, a1 = 0.f, a2 = 0.f, a3 = 0.f;
        float a4 = 0.f, a5 = 0.f, a6 = 0.f, a7 = 0.f;
        int hd = lane >> 3;
        int sA = g_csr[beg];
        int sB = (beg + 1 < end) ? g_csr[beg + 1] : sA;
        float4 lsCur = *reinterpret_cast<const float4*>(g_ls + sA * 4);
        uint4 vCur = reinterpret_cast<const uint4*>(g_hwh + (size_t)sA * 256)[lane];
        for (int i = beg; i < end; i++) {
            float4 lsv = lsCur;
            uint4 v = vCur;
            int sNext = sB;
            if (i + 2 < end) sB = g_csr[i + 2];
            if (i + 1 < end) {
                lsCur = *reinterpret_cast<const float4*>(g_ls + sNext * 4);
                vCur = reinterpret_cast<const uint4*>(g_hwh + (size_t)sNext * 256)[lane];
            }
            float l0 = lsv.x + ldv.x; l0 = l0 > 0.f ? l0 : SLOPE * l0;
            float l1 = lsv.y + ldv.y; l1 = l1 > 0.f ? l1 : SLOPE * l1;
            float l2 = lsv.z + ldv.z; l2 = l2 > 0.f ? l2 : SLOPE * l2;
            float l3 = lsv.w + ldv.w; l3 = l3 > 0.f ? l3 : SLOPE * l3;
            float p0 = __expf(l0), p1 = __expf(l1), p2 = __expf(l2), p3 = __expf(l3);
            s0 += p0; s1 += p1; s2 += p2; s3 += p3;
            float p = (hd == 0) ? p0 : (hd == 1) ? p1 : (hd == 2) ? p2 : p3;
            float2 f0 = __half22float2(*reinterpret_cast<__half2*>(&v.x));
            float2 f1 = __half22float2(*reinterpret_cast<__half2*>(&v.y));
            float2 f2 = __half22float2(*reinterpret_cast<__half2*>(&v.z));
            float2 f3 = __half22float2(*reinterpret_cast<__half2*>(&v.w));
            a0 += p * f0.x; a1 += p * f0.y; a2 += p * f1.x; a3 += p * f1.y;
            a4 += p * f2.x; a5 += p * f2.y; a6 += p * f3.x; a7 += p * f3.y;
        }
        float ss = (hd == 0) ? s0 : (hd == 1) ? s1 : (hd == 2) ? s2 : s3;
        float inv = 1.f / (ss + 1e-16f);
        const float* bp = bias + lane * 8;
        float4 bv0 = *reinterpret_cast<const float4*>(bp);
        float4 bv1 = *reinterpret_cast<const float4*>(bp + 4);
        float* op = out + (size_t)w * 256 + lane * 8;
        *reinterpret_cast<float4*>(op) =
            make_float4(a0 * inv + bv0.x, a1 * inv + bv0.y, a2 * inv + bv0.z, a3 * inv + bv0.w);
        *reinterpret_cast<float4*>(op + 4) =
            make_float4(a4 * inv + bv1.x, a5 * inv + bv1.y, a6 * inv + bv1.z, a7 * inv + bv1.w);
    } else {
        float ldh = g_ld[w];
        float ssum = 0.f;
        float ax = 0.f, ay = 0.f;
        int sA = g_csr[beg];
        int sB = (beg + 1 < end) ? g_csr[beg + 1] : sA;
        float lsCur = g_ls[sA];
        __half2 vCur = reinterpret_cast<const __half2*>(g_hwh + (size_t)sA * 64)[lane];
        for (int i = beg; i < end; i++) {
            float lsv = lsCur;
            __half2 hv = vCur;
            int sNext = sB;
            if (i + 2 < end) sB = g_csr[i + 2];
            if (i + 1 < end) {
                lsCur = g_ls[sNext];
                vCur = reinterpret_cast<const __half2*>(g_hwh + (size_t)sNext * 64)[lane];
            }
            float lg = lsv + ldh;
            lg = lg > 0.f ? lg : SLOPE * lg;
            float p = __expf(lg);
            ssum += p;
            float2 v = __half22float2(hv);
            ax += p * v.x; ay += p * v.y;
        }
        float inv = 1.f / (ssum + 1e-16f);
        float2 b = reinterpret_cast<const float2*>(bias)[lane];
        reinterpret_cast<float2*>(out + (size_t)w * 64)[lane] =
            make_float2(ax * inv + b.x, ay * inv + b.y);
    }
}

// ------------------------- ELU + BatchNorm -------------------------
__device__ __forceinline__ float eluf(float x) { return x > 0.f ? x : expm1f(x); }

__global__ void k_bn_stats() {
    int t = threadIdx.x;
    float s = 0.f, s2 = 0.f;
    for (int r = blockIdx.x; r < NN; r += gridDim.x) {
        float v = eluf(g_agg[(size_t)r * C1 + t]);
        s += v;
        s2 += v * v;
    }
    atomicAdd(&g_bnsum[t], s);
    atomicAdd(&g_bnsq[t], s2);
}

__global__ void k_bn_finalize() {
    int t = threadIdx.x;
    float mu = g_bnsum[t] / (float)NN;
    float var = g_bnsq[t] / (float)NN - mu * mu;
    g_mu[t] = mu;
    g_rstd[t] = rsqrtf(var + 1e-5f);
}

__global__ void k_bn_apply(const float* __restrict__ gam, const float* __restrict__ bet) {
    size_t i = (size_t)blockIdx.x * blockDim.x + threadIdx.x;
    if (i >= (size_t)NN * C1) return;
    int c = (int)(i & (C1 - 1));
    float v = eluf(g_agg[i]);
    g_feat[i] = (v - g_mu[c]) * g_rstd[c] * gam[c] + bet[c];
}

// ------------------------- final scorer -------------------------
__global__ void k_prep_final(const float* __restrict__ mlpW2, const float* __restrict__ mlpb2,
                             const float* __restrict__ fcW, const float* __restrict__ fcb) {
    int j = threadIdx.x;
    float s = 0.f;
    for (int k = 0; k < 64; k++) s += mlpW2[j * 64 + k] * fcW[128 + k];
    g_w2v[j] = s;
    if (j == 0) {
        float c = fcb[0];
        for (int k = 0; k < 64; k++) c += mlpb2[k] * fcW[128 + k];
        g_cb = c;
    }
}

__global__ void k_node_scalars(const float* __restrict__ fcW) {
    int w = (blockIdx.x * blockDim.x + threadIdx.x) >> 5;
    int lane = threadIdx.x & 31;
    if (w >= NN) return;
    const float* h = g_h3 + (size_t)w * 64;
    float v0 = h[lane], v1 = h[lane + 32];
    float a = v0 * fcW[lane] + v1 * fcW[lane + 32];
    float b = v0 * fcW[64 + lane] + v1 * fcW[96 + lane];
    for (int off = 16; off; off >>= 1) {
        a += __shfl_xor_sync(0xffffffffu, a, off);
        b += __shfl_xor_sync(0xffffffffu, b, off);
    }
    if (lane == 0) { g_hs[w] = a; g_hd[w] = b; }
}

// ------------------------- edge scorer: tf32 MMA edge-MLP, folded -------------------
__global__ __launch_bounds__(256) void k_edge_out(const int* __restrict__ ei,
                                                  const float* __restrict__ ea,
                                                  const float* __restrict__ mlpb1,
                                                  float* __restrict__ outp) {
    __shared__ float eas[128][17];
    __shared__ unsigned w1h[16][68];
    __shared__ unsigned w1l[16][68];
    __shared__ float b1s[64];
    __shared__ float w2vs[64];
    int t = threadIdx.x;
    int lane = t & 31;
    int wrp = t >> 5;
    int eBase = blockIdx.x * 128;

#pragma unroll
    for (int q = 0; q < 4; q++) {
        int idx = t + 256 * q;
        int k = idx >> 6, n = idx & 63;
        w1h[k][n] = g_whi[idx];
        w1l[k][n] = g_wlo[idx];
    }
    if (t < 64) { b1s[t] = mlpb1[t]; w2vs[t] = g_w2v[t]; }
#pragma unroll
    for (int q = 0; q < 2; q++) {
        int j = t + 256 * q;
        int row = j >> 2, kk = (j & 3) * 4;
        float4 v = *reinterpret_cast<const float4*>(ea + (size_t)(eBase + row) * 16 + kk);
        eas[row][kk] = v.x; eas[row][kk + 1] = v.y;
        eas[row][kk + 2] = v.z; eas[row][kk + 3] = v.w;
    }
    __syncthreads();

    int wr = wrp * 16;
    int ar = lane >> 2, ak = lane & 3;
    unsigned ahi[2][4], alo[2][4];
#pragma unroll
    for (int kf = 0; kf < 2; kf++) {
        split_tf32(eas[wr + ar][kf * 8 + ak],          ahi[kf][0], alo[kf][0]);
        split_tf32(eas[wr + ar + 8][kf * 8 + ak],      ahi[kf][1], alo[kf][1]);
        split_tf32(eas[wr + ar][kf * 8 + ak + 4],      ahi[kf][2], alo[kf][2]);
        split_tf32(eas[wr + ar + 8][kf * 8 + ak + 4],  ahi[kf][3], alo[kf][3]);
    }

    float dr0 = 0.f, dr1 = 0.f;
    int col0 = (lane & 3) * 2;
#pragma unroll
    for (int nt = 0; nt < 8; nt++) {
        float acc[4] = {0.f, 0.f, 0.f, 0.f};
        int bn = nt * 8 + (lane >> 2);
#pragma unroll
        for (int kf = 0; kf < 2; kf++) {
            int bk = kf * 8 + (lane & 3);
            unsigned bhi[2], blo[2];
            bhi[0] = w1h[bk][bn];     bhi[1] = w1h[bk + 4][bn];
            blo[0] = w1l[bk][bn];     blo[1] = w1l[bk + 4][bn];
            mma_tf32(acc, ahi[kf], bhi);
            mma_tf32(acc, alo[kf], bhi);
            mma_tf32(acc, ahi[kf], blo);
        }
        int c = nt * 8 + col0;
        float b0 = b1s[c], b1 = b1s[c + 1];
        float wv0 = w2vs[c], wv1 = w2vs[c + 1];
        dr0 += fmaxf(acc[0] + b0, 0.f) * wv0 + fmaxf(acc[1] + b1, 0.f) * wv1;
        dr1 += fmaxf(acc[2] + b0, 0.f) * wv0 + fmaxf(acc[3] + b1, 0.f) * wv1;
    }
    dr0 += __shfl_xor_sync(0xffffffffu, dr0, 1);
    dr0 += __shfl_xor_sync(0xffffffffu, dr0, 2);
    dr1 += __shfl_xor_sync(0xffffffffu, dr1, 1);
    dr1 += __shfl_xor_sync(0xffffffffu, dr1, 2);

    if ((lane & 3) == 0) {
        int r = lane >> 2;
        int e0 = eBase + wr + r;
        int e1 = e0 + 8;
        int s0 = ei[e0], d0 = ei[EE + e0];
        int s1 = ei[e1], d1 = ei[EE + e1];
        outp[e0] = g_hs[s0] + g_hd[d0] + dr0 + g_cb;
        outp[e1] = g_hs[s1] + g_hd[d1] + dr1 + g_cb;
    }
}

// ------------------------- launch -------------------------
static inline dim3 gemm_grid(int M, int Nc) { return dim3((Nc + 127) / 128, (M + 127) / 128); }

extern "C" void kernel_launch(void* const* d_in, const int* in_sizes, int n_in,
                              void* d_out, int out_size) {
    const float* x     = (const float*)d_in[0];
    const int*   ei    = (const int*)d_in[1];
    const float* ea    = (const float*)d_in[2];
    const float* W1    = (const float*)d_in[3];
    const float* a1s   = (const float*)d_in[4];
    const float* a1d   = (const float*)d_in[5];
    const float* b1    = (const float*)d_in[6];
    const float* W2    = (const float*)d_in[7];
    const float* a2s   = (const float*)d_in[8];
    const float* a2d   = (const float*)d_in[9];
    const float* b2    = (const float*)d_in[10];
    const float* W3    = (const float*)d_in[11];
    const float* a3s   = (const float*)d_in[12];
    const float* a3d   = (const float*)d_in[13];
    const float* b3    = (const float*)d_in[14];
    const float* bn1g  = (const float*)d_in[15];
    const float* bn1b  = (const float*)d_in[16];
    const float* bn2g  = (const float*)d_in[17];
    const float* bn2b  = (const float*)d_in[18];
    const float* mlpW1 = (const float*)d_in[19];
    const float* mlpb1 = (const float*)d_in[20];
    const float* mlpW2 = (const float*)d_in[21];
    const float* mlpb2 = (const float*)d_in[22];
    const float* fcW   = (const float*)d_in[23];
    const float* fcb   = (const float*)d_in[24];
    float* outp = (float*)d_out;

    static bool attrs_set = false;
    if (!attrs_set) {
        cudaFuncSetAttribute(k_gemm_bf16<0>, cudaFuncAttributeMaxDynamicSharedMemorySize, GEMM_SMEM);
        cudaFuncSetAttribute(k_gemm_bf16<1>, cudaFuncAttributeMaxDynamicSharedMemorySize, GEMM_SMEM);
        attrs_set = true;
    }

    const int PW1 = 0, PW2 = 16384, PW3 = 49152;

    k_init<<<196, 256>>>();
    k_hist<<<(EE + 255) / 256, 256>>>(ei);
    k_wsplit_pk<<<(16384 + 255) / 256, 256>>>(W1, 128, 256, PW1);
    // launch #3 (profiled): layer-1 GEMM
    k_gemm_bf16<0><<<gemm_grid(NN, C1), 256, GEMM_SMEM>>>(x, a1s, a1d, PW1, NN, 128, C1, 4);

    k_wsplit_pk<<<(32768 + 255) / 256, 256>>>(W2, 256, 256, PW2);
    k_wsplit_pk<<<(8192 + 255) / 256, 256>>>(W3, 256, 64, PW3);
    k_wsplit<<<4, 256>>>(mlpW1, 1024, 0);

    k_scan1<<<196, 256>>>();
    k_scan2<<<1, 256>>>();
    k_scan3<<<(NN + 255) / 256, 256>>>();
    k_scatter<<<(ETOT + 255) / 256, 256>>>(ei);

    const int aggBlocks = (NN * 32 + 255) / 256;
    const int bnApplyBlocks = (int)(((size_t)NN * C1 + 255) / 256);

    // ---- layer 1 (GEMM already issued)
    k_aggregate<4, 0><<<aggBlocks, 256>>>(b1);
    k_zero2<<<196, 256>>>();
    k_bn_stats<<<512, C1>>>();
    k_bn_finalize<<<1, C1>>>();
    k_bn_apply<<<bnApplyBlocks, 256>>>(bn1g, bn1b);

    // ---- layer 2
    k_gemm_bf16<1><<<gemm_grid(NN, C1), 256, GEMM_SMEM>>>(nullptr, a2s, a2d, PW2, NN, C1, C1, 4);
    k_aggregate<4, 0><<<aggBlocks, 256>>>(b2);
    k_zero2<<<196, 256>>>();
    k_bn_stats<<<512, C1>>>();
    k_bn_finalize<<<1, C1>>>();
    k_bn_apply<<<bnApplyBlocks, 256>>>(bn2g, bn2b);

    // ---- layer 3
    k_gemm_bf16<1><<<gemm_grid(NN, HIDV), 256, GEMM_SMEM>>>(nullptr, a3s, a3d, PW3, NN, C1, HIDV, 1);
    k_aggregate<1, 1><<<aggBlocks, 256>>>(b3);

    // ---- final scorer
    k_prep_final<<<1, 64>>>(mlpW2, mlpb2, fcW, fcb);
    k_node_scalars<<<(NN * 32 + 255) / 256, 256>>>(fcW);
    k_edge_out<<<12500, 256>>>(ei, ea, mlpb1, outp);

    (void)in_sizes; (void)n_in; (void)out_size;
}

// round 11
// speedup vs baseline: 1.6433x; 1.6433x over previous
#include <cuda_runtime.h>
#include <cuda_fp16.h>
#include <cuda_bf16.h>

#define NN 50000
#define EE 1600000
#define ETOT (EE + NN)
#define C1 256
#define HIDV 64
#define SLOPE 0.2f

// ------------------------- scratch (static device globals) -------------------------
__device__ __align__(16) __half g_hwh[(size_t)NN * C1];    // GEMM output fp16 (gather)
__device__ __align__(16) float  g_feat[(size_t)NN * C1];   // post-BN features
__device__ __align__(16) float  g_agg[(size_t)NN * C1];    // attention aggregate
__device__ __align__(16) float  g_h3[(size_t)NN * HIDV];   // layer-3 output
__device__ __align__(16) float  g_ls[NN * 4];
__device__ __align__(16) float  g_ld[NN * 4];
__device__ int   g_deg[NN];
__device__ int   g_off[NN + 1];
__device__ int   g_cur[NN];
__device__ int   g_csr[ETOT];
__device__ int   g_bsum[256];
__device__ float g_bnsum[C1];
__device__ float g_bnsq[C1];
__device__ float g_mu[C1];
__device__ float g_rstd[C1];
__device__ float g_w2v[HIDV];
__device__ float g_cb;
__device__ float g_hs[NN];
__device__ float g_hd[NN];
// packed bf16x2 hi/lo GEMM weights (k-pair major): W1@0(16384) W2@16384(32768) W3@49152(8192)
__device__ __align__(16) unsigned g_wbh[57344];
__device__ __align__(16) unsigned g_wbl[57344];
// tf32 hi/lo for edge-MLP W1 only
__device__ __align__(16) unsigned g_whi[1024];
__device__ __align__(16) unsigned g_wlo[1024];

// ------------------------- split helpers -------------------------
__device__ __forceinline__ void split_tf32(float x, unsigned& hi, unsigned& lo) {
    unsigned h;
    asm("cvt.rna.tf32.f32 %0, %1;" : "=r"(h) : "f"(x));
    float l = x - __uint_as_float(h);
    unsigned lb;
    asm("cvt.rna.tf32.f32 %0, %1;" : "=r"(lb) : "f"(l));
    hi = h; lo = lb;
}

__device__ __forceinline__ void split2_bf16(float x0, float x1, unsigned& hw, unsigned& lw) {
    __nv_bfloat16 h0 = __float2bfloat16_rn(x0);
    __nv_bfloat16 h1 = __float2bfloat16_rn(x1);
    __nv_bfloat16 l0 = __float2bfloat16_rn(x0 - __bfloat162float(h0));
    __nv_bfloat16 l1 = __float2bfloat16_rn(x1 - __bfloat162float(h1));
    hw = ((unsigned)__bfloat16_as_ushort(h1) << 16) | (unsigned)__bfloat16_as_ushort(h0);
    lw = ((unsigned)__bfloat16_as_ushort(l1) << 16) | (unsigned)__bfloat16_as_ushort(l0);
}

__device__ __forceinline__ void mma_bf16(float* c, const unsigned* a, const unsigned* b) {
    asm volatile("mma.sync.aligned.m16n8k16.row.col.f32.bf16.bf16.f32 "
                 "{%0,%1,%2,%3}, {%4,%5,%6,%7}, {%8,%9}, {%0,%1,%2,%3};"
                 : "+f"(c[0]), "+f"(c[1]), "+f"(c[2]), "+f"(c[3])
                 : "r"(a[0]), "r"(a[1]), "r"(a[2]), "r"(a[3]),
                   "r"(b[0]), "r"(b[1]));
}

__device__ __forceinline__ void mma_tf32(float* c, const unsigned* a, const unsigned* b) {
    asm volatile("mma.sync.aligned.m16n8k8.row.col.f32.tf32.tf32.f32 "
                 "{%0,%1,%2,%3}, {%4,%5,%6,%7}, {%8,%9}, {%0,%1,%2,%3};"
                 : "+f"(c[0]), "+f"(c[1]), "+f"(c[2]), "+f"(c[3])
                 : "r"(a[0]), "r"(a[1]), "r"(a[2]), "r"(a[3]),
                   "r"(b[0]), "r"(b[1]));
}

// ------------------------- weight pre-split kernels -------------------------
__global__ void k_wsplit_pk(const float* __restrict__ W, int Kd, int Nc, int offset) {
    int i = blockIdx.x * blockDim.x + threadIdx.x;
    int total = (Kd >> 1) * Nc;
    if (i >= total) return;
    int kp = i / Nc, n = i - kp * Nc;
    float x0 = W[(size_t)(2 * kp) * Nc + n];
    float x1 = W[(size_t)(2 * kp + 1) * Nc + n];
    unsigned hw, lw;
    split2_bf16(x0, x1, hw, lw);
    g_wbh[offset + i] = hw;
    g_wbl[offset + i] = lw;
}

__global__ void k_wsplit(const float* __restrict__ W, int count, int offset) {
    int i = blockIdx.x * blockDim.x + threadIdx.x;
    if (i < count) {
        unsigned h, l;
        split_tf32(W[i], h, l);
        g_whi[offset + i] = h;
        g_wlo[offset + i] = l;
    }
}

// ------------------------- init / zero kernels -------------------------
__global__ void k_init() {
    int i = blockIdx.x * blockDim.x + threadIdx.x;
    if (i < NN) g_deg[i] = 1;
    for (int j = i; j < NN * 4; j += 50176) { g_ls[j] = 0.f; g_ld[j] = 0.f; }
    if (i < C1) { g_bnsum[i] = 0.f; g_bnsq[i] = 0.f; }
}

__global__ void k_zero2() {
    int i = blockIdx.x * blockDim.x + threadIdx.x;
    for (int j = i; j < NN * 4; j += 50176) { g_ls[j] = 0.f; g_ld[j] = 0.f; }
    if (i < C1) { g_bnsum[i] = 0.f; g_bnsq[i] = 0.f; }
}

// ------------------------- CSR build -------------------------
__global__ void k_hist(const int* __restrict__ ei) {
    int e = blockIdx.x * blockDim.x + threadIdx.x;
    if (e < EE) atomicAdd(&g_deg[ei[EE + e]], 1);
}

__global__ void k_scan1() {
    __shared__ int sh[256];
    int t = threadIdx.x;
    int i = blockIdx.x * 256 + t;
    int v = (i < NN) ? g_deg[i] : 0;
    sh[t] = v;
    __syncthreads();
#pragma unroll
    for (int st = 1; st < 256; st <<= 1) {
        int a = (t >= st) ? sh[t - st] : 0;
        __syncthreads();
        sh[t] += a;
        __syncthreads();
    }
    if (i < NN) g_off[i] = sh[t] - v;
    if (t == 255) g_bsum[blockIdx.x] = sh[255];
}

__global__ void k_scan2() {
    __shared__ int sh[256];
    int t = threadIdx.x;
    int v = (t < 196) ? g_bsum[t] : 0;
    sh[t] = v;
    __syncthreads();
#pragma unroll
    for (int st = 1; st < 256; st <<= 1) {
        int a = (t >= st) ? sh[t - st] : 0;
        __syncthreads();
        sh[t] += a;
        __syncthreads();
    }
    g_bsum[t] = sh[t] - v;
    if (t == 255) g_off[NN] = sh[255];
}

__global__ void k_scan3() {
    int i = blockIdx.x * blockDim.x + threadIdx.x;
    if (i < NN) {
        int o = g_off[i] + g_bsum[i >> 8];
        g_off[i] = o;
        g_cur[i] = o;
    }
}

__global__ void k_scatter(const int* __restrict__ ei) {
    int e = blockIdx.x * blockDim.x + threadIdx.x;
    if (e >= ETOT) return;
    int s, d;
    if (e < EE) { s = ei[e]; d = ei[EE + e]; }
    else        { s = e - EE; d = e - EE; }
    int pos = atomicAdd(&g_cur[d], 1);
    g_csr[pos] = s;
}

// ------------------------- BF16 split GEMM: 2-stage cp.async, chunk K=32 --------------
// (identical to R9 — scalar LDS fragment loads, proven 45 µs)
#define A_STR 20
#define B_STR 132
#define O_AL  10240
#define O_BH  20480
#define O_BL  28928
#define ST_SZ 37376
#define GEMM_SMEM (2 * ST_SZ)

template <int A_SRC>
__global__ __launch_bounds__(256, 2) void k_gemm_bf16(const float* __restrict__ Aparam,
                                                      const float* __restrict__ asv,
                                                      const float* __restrict__ adv,
                                                      int boff, int M, int K, int Nc, int H) {
    const float* A = (A_SRC == 0) ? Aparam : (const float*)g_feat;
    extern __shared__ char smx[];
    unsigned smBase = (unsigned)__cvta_generic_to_shared(smx);

    int t = threadIdx.x;
    int lane = t & 31;
    int wid = t >> 5;
    int warpM = (wid & 3) * 32;
    int warpN = (wid >> 2) * 64;
    int rowBase = blockIdx.y * 128;
    int colBase = blockIdx.x * 128;

    int aRow = t >> 3, aKf = t & 7;
    int bK = t >> 5, bC = (t & 31) * 4;

    float acc[2][8][4];
#pragma unroll
    for (int mt = 0; mt < 2; mt++)
#pragma unroll
        for (int nt = 0; nt < 8; nt++)
#pragma unroll
            for (int r = 0; r < 4; r++) acc[mt][nt][r] = 0.f;

    int nCh = K >> 5;
    float4 va[4];

    auto loadA = [&](int k0) {
#pragma unroll
        for (int q = 0; q < 4; q++) {
            int gr = rowBase + aRow + 32 * q;
            va[q] = make_float4(0.f, 0.f, 0.f, 0.f);
            if (gr < M)
                va[q] = *reinterpret_cast<const float4*>(A + (size_t)gr * K + k0 + aKf * 4);
        }
    };
    auto stsA = [&](int stg) {
        unsigned* Ah = reinterpret_cast<unsigned*>(smx + stg * ST_SZ);
        unsigned* Al = reinterpret_cast<unsigned*>(smx + stg * ST_SZ + O_AL);
#pragma unroll
        for (int q = 0; q < 4; q++) {
            int row = aRow + 32 * q;
            unsigned h01, l01, h23, l23;
            split2_bf16(va[q].x, va[q].y, h01, l01);
            split2_bf16(va[q].z, va[q].w, h23, l23);
            int base = row * A_STR + aKf * 2;
            Ah[base] = h01; Ah[base + 1] = h23;
            Al[base] = l01; Al[base + 1] = l23;
        }
    };
    auto cpB = [&](int k0, int stg) {
        int kp0 = k0 >> 1;
#pragma unroll
        for (int q = 0; q < 2; q++) {
            int kk = bK + 8 * q;
            int gc = colBase + bC;
            int vbytes = (gc + 3 < Nc) ? 16 : 0;
            size_t idx = (size_t)boff + (size_t)(kp0 + kk) * Nc + (vbytes ? gc : 0);
            unsigned dH = smBase + stg * ST_SZ + O_BH + (kk * B_STR + bC) * 4;
            unsigned dL = smBase + stg * ST_SZ + O_BL + (kk * B_STR + bC) * 4;
            asm volatile("cp.async.cg.shared.global [%0], [%1], 16, %2;"
                         :: "r"(dH), "l"(g_wbh + idx), "r"(vbytes));
            asm volatile("cp.async.cg.shared.global [%0], [%1], 16, %2;"
                         :: "r"(dL), "l"(g_wbl + idx), "r"(vbytes));
        }
    };

    loadA(0);
    cpB(0, 0);
    asm volatile("cp.async.commit_group;" ::: "memory");
    stsA(0);

    int buf = 0;
    for (int c = 0; c < nCh; c++) {
        asm volatile("cp.async.wait_group 0;" ::: "memory");
        __syncthreads();
        if (c + 1 < nCh) {
            loadA((c + 1) * 32);
            cpB((c + 1) * 32, buf ^ 1);
            asm volatile("cp.async.commit_group;" ::: "memory");
        }
        {
            unsigned* Ah = reinterpret_cast<unsigned*>(smx + buf * ST_SZ);
            unsigned* Al = reinterpret_cast<unsigned*>(smx + buf * ST_SZ + O_AL);
            unsigned* Bh = reinterpret_cast<unsigned*>(smx + buf * ST_SZ + O_BH);
            unsigned* Bl = reinterpret_cast<unsigned*>(smx + buf * ST_SZ + O_BL);
            int kq = lane & 3;
            int arow = warpM + (lane >> 2);
#pragma unroll
            for (int s = 0; s < 2; s++) {
                unsigned ahi[2][4], alo[2][4];
#pragma unroll
                for (int mt = 0; mt < 2; mt++) {
                    int r0 = (arow + mt * 16) * A_STR + s * 8;
                    int r1 = r0 + 8 * A_STR;
                    ahi[mt][0] = Ah[r0 + kq];     alo[mt][0] = Al[r0 + kq];
                    ahi[mt][1] = Ah[r1 + kq];     alo[mt][1] = Al[r1 + kq];
                    ahi[mt][2] = Ah[r0 + kq + 4]; alo[mt][2] = Al[r0 + kq + 4];
                    ahi[mt][3] = Ah[r1 + kq + 4]; alo[mt][3] = Al[r1 + kq + 4];
                }
#pragma unroll
                for (int nt = 0; nt < 8; nt++) {
                    int bn = warpN + nt * 8 + (lane >> 2);
                    unsigned bhi[2], blo[2];
                    bhi[0] = Bh[(s * 8 + kq) * B_STR + bn];
                    bhi[1] = Bh[(s * 8 + kq + 4) * B_STR + bn];
                    blo[0] = Bl[(s * 8 + kq) * B_STR + bn];
                    blo[1] = Bl[(s * 8 + kq + 4) * B_STR + bn];
#pragma unroll
                    for (int mt = 0; mt < 2; mt++) {
                        mma_bf16(acc[mt][nt], ahi[mt], bhi);
                        mma_bf16(acc[mt][nt], alo[mt], bhi);
                        mma_bf16(acc[mt][nt], ahi[mt], blo);
                    }
                }
            }
        }
        if (c + 1 < nCh) stsA(buf ^ 1);
        buf ^= 1;
    }

    // epilogue: fp16 store + fused ls/ld
#pragma unroll
    for (int mt = 0; mt < 2; mt++) {
#pragma unroll
        for (int nt = 0; nt < 8; nt++) {
            int row0 = rowBase + warpM + mt * 16 + (lane >> 2);
            int col0 = colBase + warpN + nt * 8 + (lane & 3) * 2;
            if (col0 < Nc) {
                if (row0 < M)
                    *reinterpret_cast<__half2*>(g_hwh + (size_t)row0 * Nc + col0) =
                        __floats2half2_rn(acc[mt][nt][0], acc[mt][nt][1]);
                if (row0 + 8 < M)
                    *reinterpret_cast<__half2*>(g_hwh + (size_t)(row0 + 8) * Nc + col0) =
                        __floats2half2_rn(acc[mt][nt][2], acc[mt][nt][3]);
            }
        }
    }

    if (warpN < Nc) {
        int head = (colBase + warpN) >> 6;
        float pls[2][2] = {{0.f, 0.f}, {0.f, 0.f}};
        float pld[2][2] = {{0.f, 0.f}, {0.f, 0.f}};
#pragma unroll
        for (int nt = 0; nt < 8; nt++) {
            int c0 = colBase + warpN + nt * 8 + (lane & 3) * 2;
            float2 ws = *reinterpret_cast<const float2*>(asv + c0);
            float2 wd = *reinterpret_cast<const float2*>(adv + c0);
#pragma unroll
            for (int mt = 0; mt < 2; mt++) {
                pls[mt][0] += acc[mt][nt][0] * ws.x + acc[mt][nt][1] * ws.y;
                pls[mt][1] += acc[mt][nt][2] * ws.x + acc[mt][nt][3] * ws.y;
                pld[mt][0] += acc[mt][nt][0] * wd.x + acc[mt][nt][1] * wd.y;
                pld[mt][1] += acc[mt][nt][2] * wd.x + acc[mt][nt][3] * wd.y;
            }
        }
#pragma unroll
        for (int mt = 0; mt < 2; mt++)
#pragma unroll
            for (int rr = 0; rr < 2; rr++) {
                pls[mt][rr] += __shfl_xor_sync(0xffffffffu, pls[mt][rr], 1);
                pls[mt][rr] += __shfl_xor_sync(0xffffffffu, pls[mt][rr], 2);
                pld[mt][rr] += __shfl_xor_sync(0xffffffffu, pld[mt][rr], 1);
                pld[mt][rr] += __shfl_xor_sync(0xffffffffu, pld[mt][rr], 2);
            }
        if ((lane & 3) == 0) {
#pragma unroll
            for (int mt = 0; mt < 2; mt++)
#pragma unroll
                for (int rr = 0; rr < 2; rr++) {
                    int row = rowBase + warpM + mt * 16 + (lane >> 2) + rr * 8;
                    if (row < M) {
                        atomicAdd(&g_ls[row * H + head], pls[mt][rr]);
                        atomicAdd(&g_ld[row * H + head], pld[mt][rr]);
                    }
                }
        }
    }
}

// ------------------------- GAT aggregate: warp/dst, unroll-by-2 (ILP) ----------------
template <int H, int DSTSEL>
__global__ void k_aggregate(const float* __restrict__ bias) {
    float* out = (DSTSEL == 0) ? (float*)g_agg : (float*)g_h3;
    int w = (blockIdx.x * blockDim.x + threadIdx.x) >> 5;
    int lane = threadIdx.x & 31;
    if (w >= NN) return;
    int beg = g_off[w], end = g_off[w + 1];

    if (H == 4) {
        float4 ldv = *reinterpret_cast<const float4*>(g_ld + w * 4);
        float s0 = 0.f, s1 = 0.f, s2 = 0.f, s3 = 0.f;
        float a0 = 0.f, a1 = 0.f, a2 = 0.f, a3 = 0.f;
        float a4 = 0.f, a5 = 0.f, a6 = 0.f, a7 = 0.f;
        int hd = lane >> 3;
        int i = beg;
        for (; i + 1 < end; i += 2) {
            int sa = g_csr[i];
            int sb = g_csr[i + 1];
            float4 lsa = *reinterpret_cast<const float4*>(g_ls + sa * 4);
            float4 lsb = *reinterpret_cast<const float4*>(g_ls + sb * 4);
            uint4 vA = reinterpret_cast<const uint4*>(g_hwh + (size_t)sa * 256)[lane];
            uint4 vB = reinterpret_cast<const uint4*>(g_hwh + (size_t)sb * 256)[lane];

            float l0 = lsa.x + ldv.x; l0 = l0 > 0.f ? l0 : SLOPE * l0;
            float l1 = lsa.y + ldv.y; l1 = l1 > 0.f ? l1 : SLOPE * l1;
            float l2 = lsa.z + ldv.z; l2 = l2 > 0.f ? l2 : SLOPE * l2;
            float l3 = lsa.w + ldv.w; l3 = l3 > 0.f ? l3 : SLOPE * l3;
            float pa0 = __expf(l0), pa1 = __expf(l1), pa2 = __expf(l2), pa3 = __expf(l3);
            float m0 = lsb.x + ldv.x; m0 = m0 > 0.f ? m0 : SLOPE * m0;
            float m1 = lsb.y + ldv.y; m1 = m1 > 0.f ? m1 : SLOPE * m1;
            float m2 = lsb.z + ldv.z; m2 = m2 > 0.f ? m2 : SLOPE * m2;
            float m3 = lsb.w + ldv.w; m3 = m3 > 0.f ? m3 : SLOPE * m3;
            float pb0 = __expf(m0), pb1 = __expf(m1), pb2 = __expf(m2), pb3 = __expf(m3);
            s0 += pa0 + pb0; s1 += pa1 + pb1; s2 += pa2 + pb2; s3 += pa3 + pb3;
            float pA = (hd == 0) ? pa0 : (hd == 1) ? pa1 : (hd == 2) ? pa2 : pa3;
            float pB = (hd == 0) ? pb0 : (hd == 1) ? pb1 : (hd == 2) ? pb2 : pb3;

            float2 fa0 = __half22float2(*reinterpret_cast<__half2*>(&vA.x));
            float2 fa1 = __half22float2(*reinterpret_cast<__half2*>(&vA.y));
            float2 fa2 = __half22float2(*reinterpret_cast<__half2*>(&vA.z));
            float2 fa3 = __half22float2(*reinterpret_cast<__half2*>(&vA.w));
            float2 fb0 = __half22float2(*reinterpret_cast<__half2*>(&vB.x));
            float2 fb1 = __half22float2(*reinterpret_cast<__half2*>(&vB.y));
            float2 fb2 = __half22float2(*reinterpret_cast<__half2*>(&vB.z));
            float2 fb3 = __half22float2(*reinterpret_cast<__half2*>(&vB.w));
            a0 += pA * fa0.x + pB * fb0.x; a1 += pA * fa0.y + pB * fb0.y;
            a2 += pA * fa1.x + pB * fb1.x; a3 += pA * fa1.y + pB * fb1.y;
            a4 += pA * fa2.x + pB * fb2.x; a5 += pA * fa2.y + pB * fb2.y;
            a6 += pA * fa3.x + pB * fb3.x; a7 += pA * fa3.y + pB * fb3.y;
        }
        if (i < end) {
            int s = g_csr[i];
            float4 lsv = *reinterpret_cast<const float4*>(g_ls + s * 4);
            uint4 v = reinterpret_cast<const uint4*>(g_hwh + (size_t)s * 256)[lane];
            float l0 = lsv.x + ldv.x; l0 = l0 > 0.f ? l0 : SLOPE * l0;
            float l1 = lsv.y + ldv.y; l1 = l1 > 0.f ? l1 : SLOPE * l1;
            float l2 = lsv.z + ldv.z; l2 = l2 > 0.f ? l2 : SLOPE * l2;
            float l3 = lsv.w + ldv.w; l3 = l3 > 0.f ? l3 : SLOPE * l3;
            float p0 = __expf(l0), p1 = __expf(l1), p2 = __expf(l2), p3 = __expf(l3);
            s0 += p0; s1 += p1; s2 += p2; s3 += p3;
            float p = (hd == 0) ? p0 : (hd == 1) ? p1 : (hd == 2) ? p2 : p3;
            float2 f0 = __half22float2(*reinterpret_cast<__half2*>(&v.x));
            float2 f1 = __half22float2(*reinterpret_cast<__half2*>(&v.y));
            float2 f2 = __half22float2(*reinterpret_cast<__half2*>(&v.z));
            float2 f3 = __half22float2(*reinterpret_cast<__half2*>(&v.w));
            a0 += p * f0.x; a1 += p * f0.y; a2 += p * f1.x; a3 += p * f1.y;
            a4 += p * f2.x; a5 += p * f2.y; a6 += p * f3.x; a7 += p * f3.y;
        }
        float ss = (hd == 0) ? s0 : (hd == 1) ? s1 : (hd == 2) ? s2 : s3;
        float inv = 1.f / (ss + 1e-16f);
        const float* bp = bias + lane * 8;
        float4 bv0 = *reinterpret_cast<const float4*>(bp);
        float4 bv1 = *reinterpret_cast<const float4*>(bp + 4);
        float* op = out + (size_t)w * 256 + lane * 8;
        *reinterpret_cast<float4*>(op) =
            make_float4(a0 * inv + bv0.x, a1 * inv + bv0.y, a2 * inv + bv0.z, a3 * inv + bv0.w);
        *reinterpret_cast<float4*>(op + 4) =
            make_float4(a4 * inv + bv1.x, a5 * inv + bv1.y, a6 * inv + bv1.z, a7 * inv + bv1.w);
    } else {
        float ldh = g_ld[w];
        float ssum = 0.f;
        float ax = 0.f, ay = 0.f;
        int i = beg;
        for (; i + 1 < end; i += 2) {
            int sa = g_csr[i];
            int sb = g_csr[i + 1];
            float la = g_ls[sa];
            float lb = g_ls[sb];
            __half2 ha = reinterpret_cast<const __half2*>(g_hwh + (size_t)sa * 64)[lane];
            __half2 hb = reinterpret_cast<const __half2*>(g_hwh + (size_t)sb * 64)[lane];
            float lga = la + ldh; lga = lga > 0.f ? lga : SLOPE * lga;
            float lgb = lb + ldh; lgb = lgb > 0.f ? lgb : SLOPE * lgb;
            float pa = __expf(lga);
            float pb = __expf(lgb);
            ssum += pa + pb;
            float2 va = __half22float2(ha);
            float2 vb = __half22float2(hb);
            ax += pa * va.x + pb * vb.x;
            ay += pa * va.y + pb * vb.y;
        }
        if (i < end) {
            int s = g_csr[i];
            float lg = g_ls[s] + ldh;
            lg = lg > 0.f ? lg : SLOPE * lg;
            float p = __expf(lg);
            ssum += p;
            float2 v = __half22float2(
                reinterpret_cast<const __half2*>(g_hwh + (size_t)s * 64)[lane]);
            ax += p * v.x; ay += p * v.y;
        }
        float inv = 1.f / (ssum + 1e-16f);
        float2 b = reinterpret_cast<const float2*>(bias)[lane];
        reinterpret_cast<float2*>(out + (size_t)w * 64)[lane] =
            make_float2(ax * inv + b.x, ay * inv + b.y);
    }
}

// ------------------------- ELU + BatchNorm -------------------------
__device__ __forceinline__ float eluf(float x) { return x > 0.f ? x : expm1f(x); }

__global__ void k_bn_stats() {
    int t = threadIdx.x;
    float s = 0.f, s2 = 0.f;
    for (int r = blockIdx.x; r < NN; r += gridDim.x) {
        float v = eluf(g_agg[(size_t)r * C1 + t]);
        s += v;
        s2 += v * v;
    }
    atomicAdd(&g_bnsum[t], s);
    atomicAdd(&g_bnsq[t], s2);
}

__global__ void k_bn_finalize() {
    int t = threadIdx.x;
    float mu = g_bnsum[t] / (float)NN;
    float var = g_bnsq[t] / (float)NN - mu * mu;
    g_mu[t] = mu;
    g_rstd[t] = rsqrtf(var + 1e-5f);
}

__global__ void k_bn_apply(const float* __restrict__ gam, const float* __restrict__ bet) {
    size_t i = (size_t)blockIdx.x * blockDim.x + threadIdx.x;
    if (i >= (size_t)NN * C1) return;
    int c = (int)(i & (C1 - 1));
    float v = eluf(g_agg[i]);
    g_feat[i] = (v - g_mu[c]) * g_rstd[c] * gam[c] + bet[c];
}

// ------------------------- final scorer -------------------------
__global__ void k_prep_final(const float* __restrict__ mlpW2, const float* __restrict__ mlpb2,
                             const float* __restrict__ fcW, const float* __restrict__ fcb) {
    int j = threadIdx.x;
    float s = 0.f;
    for (int k = 0; k < 64; k++) s += mlpW2[j * 64 + k] * fcW[128 + k];
    g_w2v[j] = s;
    if (j == 0) {
        float c = fcb[0];
        for (int k = 0; k < 64; k++) c += mlpb2[k] * fcW[128 + k];
        g_cb = c;
    }
}

__global__ void k_node_scalars(const float* __restrict__ fcW) {
    int w = (blockIdx.x * blockDim.x + threadIdx.x) >> 5;
    int lane = threadIdx.x & 31;
    if (w >= NN) return;
    const float* h = g_h3 + (size_t)w * 64;
    float v0 = h[lane], v1 = h[lane + 32];
    float a = v0 * fcW[lane] + v1 * fcW[lane + 32];
    float b = v0 * fcW[64 + lane] + v1 * fcW[96 + lane];
    for (int off = 16; off; off >>= 1) {
        a += __shfl_xor_sync(0xffffffffu, a, off);
        b += __shfl_xor_sync(0xffffffffu, b, off);
    }
    if (lane == 0) { g_hs[w] = a; g_hd[w] = b; }
}

// ------------------------- edge scorer: tf32 MMA edge-MLP, folded -------------------
__global__ __launch_bounds__(256) void k_edge_out(const int* __restrict__ ei,
                                                  const float* __restrict__ ea,
                                                  const float* __restrict__ mlpb1,
                                                  float* __restrict__ outp) {
    __shared__ float eas[128][17];
    __shared__ unsigned w1h[16][68];
    __shared__ unsigned w1l[16][68];
    __shared__ float b1s[64];
    __shared__ float w2vs[64];
    int t = threadIdx.x;
    int lane = t & 31;
    int wrp = t >> 5;
    int eBase = blockIdx.x * 128;

#pragma unroll
    for (int q = 0; q < 4; q++) {
        int idx = t + 256 * q;
        int k = idx >> 6, n = idx & 63;
        w1h[k][n] = g_whi[idx];
        w1l[k][n] = g_wlo[idx];
    }
    if (t < 64) { b1s[t] = mlpb1[t]; w2vs[t] = g_w2v[t]; }
#pragma unroll
    for (int q = 0; q < 2; q++) {
        int j = t + 256 * q;
        int row = j >> 2, kk = (j & 3) * 4;
        float4 v = *reinterpret_cast<const float4*>(ea + (size_t)(eBase + row) * 16 + kk);
        eas[row][kk] = v.x; eas[row][kk + 1] = v.y;
        eas[row][kk + 2] = v.z; eas[row][kk + 3] = v.w;
    }
    __syncthreads();

    int wr = wrp * 16;
    int ar = lane >> 2, ak = lane & 3;
    unsigned ahi[2][4], alo[2][4];
#pragma unroll
    for (int kf = 0; kf < 2; kf++) {
        split_tf32(eas[wr + ar][kf * 8 + ak],          ahi[kf][0], alo[kf][0]);
        split_tf32(eas[wr + ar + 8][kf * 8 + ak],      ahi[kf][1], alo[kf][1]);
        split_tf32(eas[wr + ar][kf * 8 + ak + 4],      ahi[kf][2], alo[kf][2]);
        split_tf32(eas[wr + ar + 8][kf * 8 + ak + 4],  ahi[kf][3], alo[kf][3]);
    }

    float dr0 = 0.f, dr1 = 0.f;
    int col0 = (lane & 3) * 2;
#pragma unroll
    for (int nt = 0; nt < 8; nt++) {
        float acc[4] = {0.f, 0.f, 0.f, 0.f};
        int bn = nt * 8 + (lane >> 2);
#pragma unroll
        for (int kf = 0; kf < 2; kf++) {
            int bk = kf * 8 + (lane & 3);
            unsigned bhi[2], blo[2];
            bhi[0] = w1h[bk][bn];     bhi[1] = w1h[bk + 4][bn];
            blo[0] = w1l[bk][bn];     blo[1] = w1l[bk + 4][bn];
            mma_tf32(acc, ahi[kf], bhi);
            mma_tf32(acc, alo[kf], bhi);
            mma_tf32(acc, ahi[kf], blo);
        }
        int c = nt * 8 + col0;
        float b0 = b1s[c], b1 = b1s[c + 1];
        float wv0 = w2vs[c], wv1 = w2vs[c + 1];
        dr0 += fmaxf(acc[0] + b0, 0.f) * wv0 + fmaxf(acc[1] + b1, 0.f) * wv1;
        dr1 += fmaxf(acc[2] + b0, 0.f) * wv0 + fmaxf(acc[3] + b1, 0.f) * wv1;
    }
    dr0 += __shfl_xor_sync(0xffffffffu, dr0, 1);
    dr0 += __shfl_xor_sync(0xffffffffu, dr0, 2);
    dr1 += __shfl_xor_sync(0xffffffffu, dr1, 1);
    dr1 += __shfl_xor_sync(0xffffffffu, dr1, 2);

    if ((lane & 3) == 0) {
        int r = lane >> 2;
        int e0 = eBase + wr + r;
        int e1 = e0 + 8;
        int s0 = ei[e0], d0 = ei[EE + e0];
        int s1 = ei[e1], d1 = ei[EE + e1];
        outp[e0] = g_hs[s0] + g_hd[d0] + dr0 + g_cb;
        outp[e1] = g_hs[s1] + g_hd[d1] + dr1 + g_cb;
    }
}

// ------------------------- launch -------------------------
static inline dim3 gemm_grid(int M, int Nc) { return dim3((Nc + 127) / 128, (M + 127) / 128); }

extern "C" void kernel_launch(void* const* d_in, const int* in_sizes, int n_in,
                              void* d_out, int out_size) {
    const float* x     = (const float*)d_in[0];
    const int*   ei    = (const int*)d_in[1];
    const float* ea    = (const float*)d_in[2];
    const float* W1    = (const float*)d_in[3];
    const float* a1s   = (const float*)d_in[4];
    const float* a1d   = (const float*)d_in[5];
    const float* b1    = (const float*)d_in[6];
    const float* W2    = (const float*)d_in[7];
    const float* a2s   = (const float*)d_in[8];
    const float* a2d   = (const float*)d_in[9];
    const float* b2    = (const float*)d_in[10];
    const float* W3    = (const float*)d_in[11];
    const float* a3s   = (const float*)d_in[12];
    const float* a3d   = (const float*)d_in[13];
    const float* b3    = (const float*)d_in[14];
    const float* bn1g  = (const float*)d_in[15];
    const float* bn1b  = (const float*)d_in[16];
    const float* bn2g  = (const float*)d_in[17];
    const float* bn2b  = (const float*)d_in[18];
    const float* mlpW1 = (const float*)d_in[19];
    const float* mlpb1 = (const float*)d_in[20];
    const float* mlpW2 = (const float*)d_in[21];
    const float* mlpb2 = (const float*)d_in[22];
    const float* fcW   = (const float*)d_in[23];
    const float* fcb   = (const float*)d_in[24];
    float* outp = (float*)d_out;

    static bool attrs_set = false;
    if (!attrs_set) {
        cudaFuncSetAttribute(k_gemm_bf16<0>, cudaFuncAttributeMaxDynamicSharedMemorySize, GEMM_SMEM);
        cudaFuncSetAttribute(k_gemm_bf16<1>, cudaFuncAttributeMaxDynamicSharedMemorySize, GEMM_SMEM);
        attrs_set = true;
    }

    const int PW1 = 0, PW2 = 16384, PW3 = 49152;

    k_init<<<196, 256>>>();
    k_hist<<<(EE + 255) / 256, 256>>>(ei);
    k_wsplit_pk<<<(16384 + 255) / 256, 256>>>(W1, 128, 256, PW1);
    // launch #3 (profiled): layer-1 GEMM
    k_gemm_bf16<0><<<gemm_grid(NN, C1), 256, GEMM_SMEM>>>(x, a1s, a1d, PW1, NN, 128, C1, 4);

    k_wsplit_pk<<<(32768 + 255) / 256, 256>>>(W2, 256, 256, PW2);
    k_wsplit_pk<<<(8192 + 255) / 256, 256>>>(W3, 256, 64, PW3);
    k_wsplit<<<4, 256>>>(mlpW1, 1024, 0);

    k_scan1<<<196, 256>>>();
    k_scan2<<<1, 256>>>();
    k_scan3<<<(NN + 255) / 256, 256>>>();
    k_scatter<<<(ETOT + 255) / 256, 256>>>(ei);

    const int aggBlocks = (NN * 32 + 255) / 256;
    const int bnApplyBlocks = (int)(((size_t)NN * C1 + 255) / 256);

    // ---- layer 1 (GEMM already issued)
    k_aggregate<4, 0><<<aggBlocks, 256>>>(b1);
    k_zero2<<<196, 256>>>();
    k_bn_stats<<<512, C1>>>();
    k_bn_finalize<<<1, C1>>>();
    k_bn_apply<<<bnApplyBlocks, 256>>>(bn1g, bn1b);

    // ---- layer 2
    k_gemm_bf16<1><<<gemm_grid(NN, C1), 256, GEMM_SMEM>>>(nullptr, a2s, a2d, PW2, NN, C1, C1, 4);
    k_aggregate<4, 0><<<aggBlocks, 256>>>(b2);
    k_zero2<<<196, 256>>>();
    k_bn_stats<<<512, C1>>>();
    k_bn_finalize<<<1, C1>>>();
    k_bn_apply<<<bnApplyBlocks, 256>>>(bn2g, bn2b);

    // ---- layer 3
    k_gemm_bf16<1><<<gemm_grid(NN, HIDV), 256, GEMM_SMEM>>>(nullptr, a3s, a3d, PW3, NN, C1, HIDV, 1);
    k_aggregate<1, 1><<<aggBlocks, 256>>>(b3);

    // ---- final scorer
    k_prep_final<<<1, 64>>>(mlpW2, mlpb2, fcW, fcb);
    k_node_scalars<<<(NN * 32 + 255) / 256, 256>>>(fcW);
    k_edge_out<<<12500, 256>>>(ei, ea, mlpb1, outp);

    (void)in_sizes; (void)n_in; (void)out_size;
}

// round 12
// speedup vs baseline: 1.6603x; 1.0103x over previous
#include <cuda_runtime.h>
#include <cuda_fp16.h>
#include <cuda_bf16.h>

#define NN 50000
#define EE 1600000
#define ETOT (EE + NN)
#define C1 256
#define HIDV 64
#define SLOPE 0.2f

// ------------------------- scratch (static device globals) -------------------------
__device__ __align__(16) __half g_hwh[(size_t)NN * C1];    // GEMM output fp16 (gather)
__device__ __align__(16) float  g_feat[(size_t)NN * C1];   // post-BN features
__device__ __align__(16) float  g_agg[(size_t)NN * C1];    // attention aggregate
__device__ __align__(16) float  g_h3[(size_t)NN * HIDV];   // layer-3 output
__device__ __align__(16) float  g_ls[NN * 4];
__device__ __align__(16) float  g_ld[NN * 4];
__device__ int   g_deg[NN];
__device__ int   g_off[NN + 1];
__device__ int   g_cur[NN];
__device__ int   g_csr[ETOT];
__device__ int   g_bsum[256];
__device__ float g_bnsum[C1];
__device__ float g_bnsq[C1];
__device__ float g_mu[C1];
__device__ float g_rstd[C1];
__device__ float g_w2v[HIDV];
__device__ float g_cb;
__device__ float g_hs[NN];
__device__ float g_hd[NN];
// packed bf16x2 hi/lo GEMM weights (k-pair major): W1@0(16384) W2@16384(32768) W3@49152(8192)
__device__ __align__(16) unsigned g_wbh[57344];
__device__ __align__(16) unsigned g_wbl[57344];
// packed bf16x2 hi/lo for edge-MLP W1: [8 k-pairs][64] = 512 words
__device__ __align__(16) unsigned g_whi[512];
__device__ __align__(16) unsigned g_wlo[512];

// ------------------------- split helpers -------------------------
__device__ __forceinline__ void split2_bf16(float x0, float x1, unsigned& hw, unsigned& lw) {
    __nv_bfloat16 h0 = __float2bfloat16_rn(x0);
    __nv_bfloat16 h1 = __float2bfloat16_rn(x1);
    __nv_bfloat16 l0 = __float2bfloat16_rn(x0 - __bfloat162float(h0));
    __nv_bfloat16 l1 = __float2bfloat16_rn(x1 - __bfloat162float(h1));
    hw = ((unsigned)__bfloat16_as_ushort(h1) << 16) | (unsigned)__bfloat16_as_ushort(h0);
    lw = ((unsigned)__bfloat16_as_ushort(l1) << 16) | (unsigned)__bfloat16_as_ushort(l0);
}

__device__ __forceinline__ void mma_bf16(float* c, const unsigned* a, const unsigned* b) {
    asm volatile("mma.sync.aligned.m16n8k16.row.col.f32.bf16.bf16.f32 "
                 "{%0,%1,%2,%3}, {%4,%5,%6,%7}, {%8,%9}, {%0,%1,%2,%3};"
                 : "+f"(c[0]), "+f"(c[1]), "+f"(c[2]), "+f"(c[3])
                 : "r"(a[0]), "r"(a[1]), "r"(a[2]), "r"(a[3]),
                   "r"(b[0]), "r"(b[1]));
}

// ------------------------- weight pre-split kernels -------------------------
__global__ void k_wsplit_pk(const float* __restrict__ W, int Kd, int Nc, int offset) {
    int i = blockIdx.x * blockDim.x + threadIdx.x;
    int total = (Kd >> 1) * Nc;
    if (i >= total) return;
    int kp = i / Nc, n = i - kp * Nc;
    float x0 = W[(size_t)(2 * kp) * Nc + n];
    float x1 = W[(size_t)(2 * kp + 1) * Nc + n];
    unsigned hw, lw;
    split2_bf16(x0, x1, hw, lw);
    g_wbh[offset + i] = hw;
    g_wbl[offset + i] = lw;
}

// edge-MLP W1 [16,64] -> packed bf16x2 k-pair major [8][64]
__global__ void k_wsplit_mlp(const float* __restrict__ W) {
    int i = blockIdx.x * blockDim.x + threadIdx.x;   // 512
    if (i >= 512) return;
    int kp = i >> 6, n = i & 63;
    float x0 = W[(2 * kp) * 64 + n];
    float x1 = W[(2 * kp + 1) * 64 + n];
    unsigned hw, lw;
    split2_bf16(x0, x1, hw, lw);
    g_whi[i] = hw;
    g_wlo[i] = lw;
}

// ------------------------- init / zero kernels -------------------------
__global__ void k_init() {
    int i = blockIdx.x * blockDim.x + threadIdx.x;
    if (i < NN) g_deg[i] = 1;
    for (int j = i; j < NN * 4; j += 50176) { g_ls[j] = 0.f; g_ld[j] = 0.f; }
    if (i < C1) { g_bnsum[i] = 0.f; g_bnsq[i] = 0.f; }
}

__global__ void k_zero2() {
    int i = blockIdx.x * blockDim.x + threadIdx.x;
    for (int j = i; j < NN * 4; j += 50176) { g_ls[j] = 0.f; g_ld[j] = 0.f; }
    if (i < C1) { g_bnsum[i] = 0.f; g_bnsq[i] = 0.f; }
}

// ------------------------- CSR build -------------------------
__global__ void k_hist(const int* __restrict__ ei) {
    int e = blockIdx.x * blockDim.x + threadIdx.x;
    if (e < EE) atomicAdd(&g_deg[ei[EE + e]], 1);
}

__global__ void k_scan1() {
    __shared__ int sh[256];
    int t = threadIdx.x;
    int i = blockIdx.x * 256 + t;
    int v = (i < NN) ? g_deg[i] : 0;
    sh[t] = v;
    __syncthreads();
#pragma unroll
    for (int st = 1; st < 256; st <<= 1) {
        int a = (t >= st) ? sh[t - st] : 0;
        __syncthreads();
        sh[t] += a;
        __syncthreads();
    }
    if (i < NN) g_off[i] = sh[t] - v;
    if (t == 255) g_bsum[blockIdx.x] = sh[255];
}

__global__ void k_scan2() {
    __shared__ int sh[256];
    int t = threadIdx.x;
    int v = (t < 196) ? g_bsum[t] : 0;
    sh[t] = v;
    __syncthreads();
#pragma unroll
    for (int st = 1; st < 256; st <<= 1) {
        int a = (t >= st) ? sh[t - st] : 0;
        __syncthreads();
        sh[t] += a;
        __syncthreads();
    }
    g_bsum[t] = sh[t] - v;
    if (t == 255) g_off[NN] = sh[255];
}

__global__ void k_scan3() {
    int i = blockIdx.x * blockDim.x + threadIdx.x;
    if (i < NN) {
        int o = g_off[i] + g_bsum[i >> 8];
        g_off[i] = o;
        g_cur[i] = o;
    }
}

__global__ void k_scatter(const int* __restrict__ ei) {
    int e = blockIdx.x * blockDim.x + threadIdx.x;
    if (e >= ETOT) return;
    int s, d;
    if (e < EE) { s = ei[e]; d = ei[EE + e]; }
    else        { s = e - EE; d = e - EE; }
    int pos = atomicAdd(&g_cur[d], 1);
    g_csr[pos] = s;
}

// ------------------------- BF16 split GEMM: 2-stage cp.async, chunk K=32 --------------
#define A_STR 20
#define B_STR 132
#define O_AL  10240
#define O_BH  20480
#define O_BL  28928
#define ST_SZ 37376
#define GEMM_SMEM (2 * ST_SZ)

template <int A_SRC>
__global__ __launch_bounds__(256, 2) void k_gemm_bf16(const float* __restrict__ Aparam,
                                                      const float* __restrict__ asv,
                                                      const float* __restrict__ adv,
                                                      int boff, int M, int K, int Nc, int H) {
    const float* A = (A_SRC == 0) ? Aparam : (const float*)g_feat;
    extern __shared__ char smx[];
    unsigned smBase = (unsigned)__cvta_generic_to_shared(smx);

    int t = threadIdx.x;
    int lane = t & 31;
    int wid = t >> 5;
    int warpM = (wid & 3) * 32;
    int warpN = (wid >> 2) * 64;
    int rowBase = blockIdx.y * 128;
    int colBase = blockIdx.x * 128;

    int aRow = t >> 3, aKf = t & 7;
    int bK = t >> 5, bC = (t & 31) * 4;

    float acc[2][8][4];
#pragma unroll
    for (int mt = 0; mt < 2; mt++)
#pragma unroll
        for (int nt = 0; nt < 8; nt++)
#pragma unroll
            for (int r = 0; r < 4; r++) acc[mt][nt][r] = 0.f;

    int nCh = K >> 5;
    float4 va[4];

    auto loadA = [&](int k0) {
#pragma unroll
        for (int q = 0; q < 4; q++) {
            int gr = rowBase + aRow + 32 * q;
            va[q] = make_float4(0.f, 0.f, 0.f, 0.f);
            if (gr < M)
                va[q] = *reinterpret_cast<const float4*>(A + (size_t)gr * K + k0 + aKf * 4);
        }
    };
    auto stsA = [&](int stg) {
        unsigned* Ah = reinterpret_cast<unsigned*>(smx + stg * ST_SZ);
        unsigned* Al = reinterpret_cast<unsigned*>(smx + stg * ST_SZ + O_AL);
#pragma unroll
        for (int q = 0; q < 4; q++) {
            int row = aRow + 32 * q;
            unsigned h01, l01, h23, l23;
            split2_bf16(va[q].x, va[q].y, h01, l01);
            split2_bf16(va[q].z, va[q].w, h23, l23);
            int base = row * A_STR + aKf * 2;
            Ah[base] = h01; Ah[base + 1] = h23;
            Al[base] = l01; Al[base + 1] = l23;
        }
    };
    auto cpB = [&](int k0, int stg) {
        int kp0 = k0 >> 1;
#pragma unroll
        for (int q = 0; q < 2; q++) {
            int kk = bK + 8 * q;
            int gc = colBase + bC;
            int vbytes = (gc + 3 < Nc) ? 16 : 0;
            size_t idx = (size_t)boff + (size_t)(kp0 + kk) * Nc + (vbytes ? gc : 0);
            unsigned dH = smBase + stg * ST_SZ + O_BH + (kk * B_STR + bC) * 4;
            unsigned dL = smBase + stg * ST_SZ + O_BL + (kk * B_STR + bC) * 4;
            asm volatile("cp.async.cg.shared.global [%0], [%1], 16, %2;"
                         :: "r"(dH), "l"(g_wbh + idx), "r"(vbytes));
            asm volatile("cp.async.cg.shared.global [%0], [%1], 16, %2;"
                         :: "r"(dL), "l"(g_wbl + idx), "r"(vbytes));
        }
    };

    loadA(0);
    cpB(0, 0);
    asm volatile("cp.async.commit_group;" ::: "memory");
    stsA(0);

    int buf = 0;
    for (int c = 0; c < nCh; c++) {
        asm volatile("cp.async.wait_group 0;" ::: "memory");
        __syncthreads();
        if (c + 1 < nCh) {
            loadA((c + 1) * 32);
            cpB((c + 1) * 32, buf ^ 1);
            asm volatile("cp.async.commit_group;" ::: "memory");
        }
        {
            unsigned* Ah = reinterpret_cast<unsigned*>(smx + buf * ST_SZ);
            unsigned* Al = reinterpret_cast<unsigned*>(smx + buf * ST_SZ + O_AL);
            unsigned* Bh = reinterpret_cast<unsigned*>(smx + buf * ST_SZ + O_BH);
            unsigned* Bl = reinterpret_cast<unsigned*>(smx + buf * ST_SZ + O_BL);
            int kq = lane & 3;
            int arow = warpM + (lane >> 2);
#pragma unroll
            for (int s = 0; s < 2; s++) {
                unsigned ahi[2][4], alo[2][4];
#pragma unroll
                for (int mt = 0; mt < 2; mt++) {
                    int r0 = (arow + mt * 16) * A_STR + s * 8;
                    int r1 = r0 + 8 * A_STR;
                    ahi[mt][0] = Ah[r0 + kq];     alo[mt][0] = Al[r0 + kq];
                    ahi[mt][1] = Ah[r1 + kq];     alo[mt][1] = Al[r1 + kq];
                    ahi[mt][2] = Ah[r0 + kq + 4]; alo[mt][2] = Al[r0 + kq + 4];
                    ahi[mt][3] = Ah[r1 + kq + 4]; alo[mt][3] = Al[r1 + kq + 4];
                }
#pragma unroll
                for (int nt = 0; nt < 8; nt++) {
                    int bn = warpN + nt * 8 + (lane >> 2);
                    unsigned bhi[2], blo[2];
                    bhi[0] = Bh[(s * 8 + kq) * B_STR + bn];
                    bhi[1] = Bh[(s * 8 + kq + 4) * B_STR + bn];
                    blo[0] = Bl[(s * 8 + kq) * B_STR + bn];
                    blo[1] = Bl[(s * 8 + kq + 4) * B_STR + bn];
#pragma unroll
                    for (int mt = 0; mt < 2; mt++) {
                        mma_bf16(acc[mt][nt], ahi[mt], bhi);
                        mma_bf16(acc[mt][nt], alo[mt], bhi);
                        mma_bf16(acc[mt][nt], ahi[mt], blo);
                    }
                }
            }
        }
        if (c + 1 < nCh) stsA(buf ^ 1);
        buf ^= 1;
    }

    // epilogue: fp16 store + fused ls/ld
#pragma unroll
    for (int mt = 0; mt < 2; mt++) {
#pragma unroll
        for (int nt = 0; nt < 8; nt++) {
            int row0 = rowBase + warpM + mt * 16 + (lane >> 2);
            int col0 = colBase + warpN + nt * 8 + (lane & 3) * 2;
            if (col0 < Nc) {
                if (row0 < M)
                    *reinterpret_cast<__half2*>(g_hwh + (size_t)row0 * Nc + col0) =
                        __floats2half2_rn(acc[mt][nt][0], acc[mt][nt][1]);
                if (row0 + 8 < M)
                    *reinterpret_cast<__half2*>(g_hwh + (size_t)(row0 + 8) * Nc + col0) =
                        __floats2half2_rn(acc[mt][nt][2], acc[mt][nt][3]);
            }
        }
    }

    if (warpN < Nc) {
        int head = (colBase + warpN) >> 6;
        float pls[2][2] = {{0.f, 0.f}, {0.f, 0.f}};
        float pld[2][2] = {{0.f, 0.f}, {0.f, 0.f}};
#pragma unroll
        for (int nt = 0; nt < 8; nt++) {
            int c0 = colBase + warpN + nt * 8 + (lane & 3) * 2;
            float2 ws = *reinterpret_cast<const float2*>(asv + c0);
            float2 wd = *reinterpret_cast<const float2*>(adv + c0);
#pragma unroll
            for (int mt = 0; mt < 2; mt++) {
                pls[mt][0] += acc[mt][nt][0] * ws.x + acc[mt][nt][1] * ws.y;
                pls[mt][1] += acc[mt][nt][2] * ws.x + acc[mt][nt][3] * ws.y;
                pld[mt][0] += acc[mt][nt][0] * wd.x + acc[mt][nt][1] * wd.y;
                pld[mt][1] += acc[mt][nt][2] * wd.x + acc[mt][nt][3] * wd.y;
            }
        }
#pragma unroll
        for (int mt = 0; mt < 2; mt++)
#pragma unroll
            for (int rr = 0; rr < 2; rr++) {
                pls[mt][rr] += __shfl_xor_sync(0xffffffffu, pls[mt][rr], 1);
                pls[mt][rr] += __shfl_xor_sync(0xffffffffu, pls[mt][rr], 2);
                pld[mt][rr] += __shfl_xor_sync(0xffffffffu, pld[mt][rr], 1);
                pld[mt][rr] += __shfl_xor_sync(0xffffffffu, pld[mt][rr], 2);
            }
        if ((lane & 3) == 0) {
#pragma unroll
            for (int mt = 0; mt < 2; mt++)
#pragma unroll
                for (int rr = 0; rr < 2; rr++) {
                    int row = rowBase + warpM + mt * 16 + (lane >> 2) + rr * 8;
                    if (row < M) {
                        atomicAdd(&g_ls[row * H + head], pls[mt][rr]);
                        atomicAdd(&g_ld[row * H + head], pld[mt][rr]);
                    }
                }
        }
    }
}

// ------------------------- GAT aggregate: warp/dst, unroll-by-4 (ILP) ----------------
template <int H, int DSTSEL>
__global__ void k_aggregate(const float* __restrict__ bias) {
    float* out = (DSTSEL == 0) ? (float*)g_agg : (float*)g_h3;
    int w = (blockIdx.x * blockDim.x + threadIdx.x) >> 5;
    int lane = threadIdx.x & 31;
    if (w >= NN) return;
    int beg = g_off[w], end = g_off[w + 1];

    if (H == 4) {
        float4 ldv = *reinterpret_cast<const float4*>(g_ld + w * 4);
        float s0 = 0.f, s1 = 0.f, s2 = 0.f, s3 = 0.f;
        float a0 = 0.f, a1 = 0.f, a2 = 0.f, a3 = 0.f;
        float a4 = 0.f, a5 = 0.f, a6 = 0.f, a7 = 0.f;
        int hd = lane >> 3;
        int i = beg;
        for (; i + 3 < end; i += 4) {
            int sx[4];
            float4 lsx[4];
            uint4 vx[4];
#pragma unroll
            for (int u = 0; u < 4; u++) sx[u] = g_csr[i + u];
#pragma unroll
            for (int u = 0; u < 4; u++) {
                lsx[u] = *reinterpret_cast<const float4*>(g_ls + sx[u] * 4);
                vx[u] = reinterpret_cast<const uint4*>(g_hwh + (size_t)sx[u] * 256)[lane];
            }
#pragma unroll
            for (int u = 0; u < 4; u++) {
                float l0 = lsx[u].x + ldv.x; l0 = l0 > 0.f ? l0 : SLOPE * l0;
                float l1 = lsx[u].y + ldv.y; l1 = l1 > 0.f ? l1 : SLOPE * l1;
                float l2 = lsx[u].z + ldv.z; l2 = l2 > 0.f ? l2 : SLOPE * l2;
                float l3 = lsx[u].w + ldv.w; l3 = l3 > 0.f ? l3 : SLOPE * l3;
                float p0 = __expf(l0), p1 = __expf(l1), p2 = __expf(l2), p3 = __expf(l3);
                s0 += p0; s1 += p1; s2 += p2; s3 += p3;
                float p = (hd == 0) ? p0 : (hd == 1) ? p1 : (hd == 2) ? p2 : p3;
                float2 f0 = __half22float2(*reinterpret_cast<__half2*>(&vx[u].x));
                float2 f1 = __half22float2(*reinterpret_cast<__half2*>(&vx[u].y));
                float2 f2 = __half22float2(*reinterpret_cast<__half2*>(&vx[u].z));
                float2 f3 = __half22float2(*reinterpret_cast<__half2*>(&vx[u].w));
                a0 += p * f0.x; a1 += p * f0.y; a2 += p * f1.x; a3 += p * f1.y;
                a4 += p * f2.x; a5 += p * f2.y; a6 += p * f3.x; a7 += p * f3.y;
            }
        }
        for (; i < end; i++) {
            int s = g_csr[i];
            float4 lsv = *reinterpret_cast<const float4*>(g_ls + s * 4);
            uint4 v = reinterpret_cast<const uint4*>(g_hwh + (size_t)s * 256)[lane];
            float l0 = lsv.x + ldv.x; l0 = l0 > 0.f ? l0 : SLOPE * l0;
            float l1 = lsv.y + ldv.y; l1 = l1 > 0.f ? l1 : SLOPE * l1;
            float l2 = lsv.z + ldv.z; l2 = l2 > 0.f ? l2 : SLOPE * l2;
            float l3 = lsv.w + ldv.w; l3 = l3 > 0.f ? l3 : SLOPE * l3;
            float p0 = __expf(l0), p1 = __expf(l1), p2 = __expf(l2), p3 = __expf(l3);
            s0 += p0; s1 += p1; s2 += p2; s3 += p3;
            float p = (hd == 0) ? p0 : (hd == 1) ? p1 : (hd == 2) ? p2 : p3;
            float2 f0 = __half22float2(*reinterpret_cast<__half2*>(&v.x));
            float2 f1 = __half22float2(*reinterpret_cast<__half2*>(&v.y));
            float2 f2 = __half22float2(*reinterpret_cast<__half2*>(&v.z));
            float2 f3 = __half22float2(*reinterpret_cast<__half2*>(&v.w));
            a0 += p * f0.x; a1 += p * f0.y; a2 += p * f1.x; a3 += p * f1.y;
            a4 += p * f2.x; a5 += p * f2.y; a6 += p * f3.x; a7 += p * f3.y;
        }
        float ss = (hd == 0) ? s0 : (hd == 1) ? s1 : (hd == 2) ? s2 : s3;
        float inv = 1.f / (ss + 1e-16f);
        const float* bp = bias + lane * 8;
        float4 bv0 = *reinterpret_cast<const float4*>(bp);
        float4 bv1 = *reinterpret_cast<const float4*>(bp + 4);
        float* op = out + (size_t)w * 256 + lane * 8;
        *reinterpret_cast<float4*>(op) =
            make_float4(a0 * inv + bv0.x, a1 * inv + bv0.y, a2 * inv + bv0.z, a3 * inv + bv0.w);
        *reinterpret_cast<float4*>(op + 4) =
            make_float4(a4 * inv + bv1.x, a5 * inv + bv1.y, a6 * inv + bv1.z, a7 * inv + bv1.w);
    } else {
        float ldh = g_ld[w];
        float ssum = 0.f;
        float ax = 0.f, ay = 0.f;
        int i = beg;
        for (; i + 1 < end; i += 2) {
            int sa = g_csr[i];
            int sb = g_csr[i + 1];
            float la = g_ls[sa];
            float lb = g_ls[sb];
            __half2 ha = reinterpret_cast<const __half2*>(g_hwh + (size_t)sa * 64)[lane];
            __half2 hb = reinterpret_cast<const __half2*>(g_hwh + (size_t)sb * 64)[lane];
            float lga = la + ldh; lga = lga > 0.f ? lga : SLOPE * lga;
            float lgb = lb + ldh; lgb = lgb > 0.f ? lgb : SLOPE * lgb;
            float pa = __expf(lga);
            float pb = __expf(lgb);
            ssum += pa + pb;
            float2 va = __half22float2(ha);
            float2 vb = __half22float2(hb);
            ax += pa * va.x + pb * vb.x;
            ay += pa * va.y + pb * vb.y;
        }
        if (i < end) {
            int s = g_csr[i];
            float lg = g_ls[s] + ldh;
            lg = lg > 0.f ? lg : SLOPE * lg;
            float p = __expf(lg);
            ssum += p;
            float2 v = __half22float2(
                reinterpret_cast<const __half2*>(g_hwh + (size_t)s * 64)[lane]);
            ax += p * v.x; ay += p * v.y;
        }
        float inv = 1.f / (ssum + 1e-16f);
        float2 b = reinterpret_cast<const float2*>(bias)[lane];
        reinterpret_cast<float2*>(out + (size_t)w * 64)[lane] =
            make_float2(ax * inv + b.x, ay * inv + b.y);
    }
}

// ------------------------- ELU + BatchNorm -------------------------
__device__ __forceinline__ float eluf(float x) { return x > 0.f ? x : expm1f(x); }

__global__ void k_bn_stats() {
    int t = threadIdx.x;
    float s = 0.f, s2 = 0.f;
    for (int r = blockIdx.x; r < NN; r += gridDim.x) {
        float v = eluf(g_agg[(size_t)r * C1 + t]);
        s += v;
        s2 += v * v;
    }
    atomicAdd(&g_bnsum[t], s);
    atomicAdd(&g_bnsq[t], s2);
}

__global__ void k_bn_finalize() {
    int t = threadIdx.x;
    float mu = g_bnsum[t] / (float)NN;
    float var = g_bnsq[t] / (float)NN - mu * mu;
    g_mu[t] = mu;
    g_rstd[t] = rsqrtf(var + 1e-5f);
}

__global__ void k_bn_apply(const float* __restrict__ gam, const float* __restrict__ bet) {
    size_t i = (size_t)blockIdx.x * blockDim.x + threadIdx.x;
    if (i >= (size_t)NN * C1) return;
    int c = (int)(i & (C1 - 1));
    float v = eluf(g_agg[i]);
    g_feat[i] = (v - g_mu[c]) * g_rstd[c] * gam[c] + bet[c];
}

// ------------------------- final scorer -------------------------
__global__ void k_prep_final(const float* __restrict__ mlpW2, const float* __restrict__ mlpb2,
                             const float* __restrict__ fcW, const float* __restrict__ fcb) {
    int j = threadIdx.x;
    float s = 0.f;
    for (int k = 0; k < 64; k++) s += mlpW2[j * 64 + k] * fcW[128 + k];
    g_w2v[j] = s;
    if (j == 0) {
        float c = fcb[0];
        for (int k = 0; k < 64; k++) c += mlpb2[k] * fcW[128 + k];
        g_cb = c;
    }
}

__global__ void k_node_scalars(const float* __restrict__ fcW) {
    int w = (blockIdx.x * blockDim.x + threadIdx.x) >> 5;
    int lane = threadIdx.x & 31;
    if (w >= NN) return;
    const float* h = g_h3 + (size_t)w * 64;
    float v0 = h[lane], v1 = h[lane + 32];
    float a = v0 * fcW[lane] + v1 * fcW[lane + 32];
    float b = v0 * fcW[64 + lane] + v1 * fcW[96 + lane];
    for (int off = 16; off; off >>= 1) {
        a += __shfl_xor_sync(0xffffffffu, a, off);
        b += __shfl_xor_sync(0xffffffffu, b, off);
    }
    if (lane == 0) { g_hs[w] = a; g_hd[w] = b; }
}

// ------------------------- edge scorer: bf16 split MMA edge-MLP, folded ---------------
// K=16 -> one m16n8k16 per n-tile per term. Edge attrs staged pre-split bf16x2.
__global__ __launch_bounds__(256) void k_edge_out(const int* __restrict__ ei,
                                                  const float* __restrict__ ea,
                                                  const float* __restrict__ mlpb1,
                                                  float* __restrict__ outp) {
    __shared__ unsigned easH[128][9];   // 8 k-pair words + pad
    __shared__ unsigned easL[128][9];
    __shared__ unsigned w1h[8][68];
    __shared__ unsigned w1l[8][68];
    __shared__ float b1s[64];
    __shared__ float w2vs[64];
    int t = threadIdx.x;
    int lane = t & 31;
    int wrp = t >> 5;
    int eBase = blockIdx.x * 128;

    // stage mlp weights (hi/lo packed bf16x2) + bias + w2v
#pragma unroll
    for (int q = 0; q < 2; q++) {
        int idx = t + 256 * q;  // 512
        int k = idx >> 6, n = idx & 63;
        w1h[k][n] = g_whi[idx];
        w1l[k][n] = g_wlo[idx];
    }
    if (t < 64) { b1s[t] = mlpb1[t]; w2vs[t] = g_w2v[t]; }
    // stage edge attrs 128x16 with bf16 split (each float4 = 2 k-pairs)
#pragma unroll
    for (int q = 0; q < 2; q++) {
        int j = t + 256 * q;          // 512 float4s
        int row = j >> 2, kp = (j & 3) * 2;
        float4 v = *reinterpret_cast<const float4*>(ea + (size_t)(eBase + row) * 16 + kp * 2);
        unsigned h0, l0, h1, l1;
        split2_bf16(v.x, v.y, h0, l0);
        split2_bf16(v.z, v.w, h1, l1);
        easH[row][kp] = h0; easH[row][kp + 1] = h1;
        easL[row][kp] = l0; easL[row][kp + 1] = l1;
    }
    __syncthreads();

    int wr = wrp * 16;
    int ar = lane >> 2, kq = lane & 3;
    unsigned ah[4], al[4];
    ah[0] = easH[wr + ar][kq];       al[0] = easL[wr + ar][kq];
    ah[1] = easH[wr + ar + 8][kq];   al[1] = easL[wr + ar + 8][kq];
    ah[2] = easH[wr + ar][kq + 4];   al[2] = easL[wr + ar][kq + 4];
    ah[3] = easH[wr + ar + 8][kq + 4]; al[3] = easL[wr + ar + 8][kq + 4];

    float dr0 = 0.f, dr1 = 0.f;
    int col0 = (lane & 3) * 2;
#pragma unroll
    for (int nt = 0; nt < 8; nt++) {
        float acc[4] = {0.f, 0.f, 0.f, 0.f};
        int bn = nt * 8 + (lane >> 2);
        unsigned bh[2], bl[2];
        bh[0] = w1h[kq][bn];     bh[1] = w1h[kq + 4][bn];
        bl[0] = w1l[kq][bn];     bl[1] = w1l[kq + 4][bn];
        mma_bf16(acc, ah, bh);
        mma_bf16(acc, al, bh);
        mma_bf16(acc, ah, bl);
        int c = nt * 8 + col0;
        float b0 = b1s[c], b1 = b1s[c + 1];
        float wv0 = w2vs[c], wv1 = w2vs[c + 1];
        dr0 += fmaxf(acc[0] + b0, 0.f) * wv0 + fmaxf(acc[1] + b1, 0.f) * wv1;
        dr1 += fmaxf(acc[2] + b0, 0.f) * wv0 + fmaxf(acc[3] + b1, 0.f) * wv1;
    }
    dr0 += __shfl_xor_sync(0xffffffffu, dr0, 1);
    dr0 += __shfl_xor_sync(0xffffffffu, dr0, 2);
    dr1 += __shfl_xor_sync(0xffffffffu, dr1, 1);
    dr1 += __shfl_xor_sync(0xffffffffu, dr1, 2);

    if ((lane & 3) == 0) {
        int r = lane >> 2;
        int e0 = eBase + wr + r;
        int e1 = e0 + 8;
        int s0 = ei[e0], d0 = ei[EE + e0];
        int s1 = ei[e1], d1 = ei[EE + e1];
        outp[e0] = g_hs[s0] + g_hd[d0] + dr0 + g_cb;
        outp[e1] = g_hs[s1] + g_hd[d1] + dr1 + g_cb;
    }
}

// ------------------------- launch -------------------------
static inline dim3 gemm_grid(int M, int Nc) { return dim3((Nc + 127) / 128, (M + 127) / 128); }

extern "C" void kernel_launch(void* const* d_in, const int* in_sizes, int n_in,
                              void* d_out, int out_size) {
    const float* x     = (const float*)d_in[0];
    const int*   ei    = (const int*)d_in[1];
    const float* ea    = (const float*)d_in[2];
    const float* W1    = (const float*)d_in[3];
    const float* a1s   = (const float*)d_in[4];
    const float* a1d   = (const float*)d_in[5];
    const float* b1    = (const float*)d_in[6];
    const float* W2    = (const float*)d_in[7];
    const float* a2s   = (const float*)d_in[8];
    const float* a2d   = (const float*)d_in[9];
    const float* b2    = (const float*)d_in[10];
    const float* W3    = (const float*)d_in[11];
    const float* a3s   = (const float*)d_in[12];
    const float* a3d   = (const float*)d_in[13];
    const float* b3    = (const float*)d_in[14];
    const float* bn1g  = (const float*)d_in[15];
    const float* bn1b  = (const float*)d_in[16];
    const float* bn2g  = (const float*)d_in[17];
    const float* bn2b  = (const float*)d_in[18];
    const float* mlpW1 = (const float*)d_in[19];
    const float* mlpb1 = (const float*)d_in[20];
    const float* mlpW2 = (const float*)d_in[21];
    const float* mlpb2 = (const float*)d_in[22];
    const float* fcW   = (const float*)d_in[23];
    const float* fcb   = (const float*)d_in[24];
    float* outp = (float*)d_out;

    static bool attrs_set = false;
    if (!attrs_set) {
        cudaFuncSetAttribute(k_gemm_bf16<0>, cudaFuncAttributeMaxDynamicSharedMemorySize, GEMM_SMEM);
        cudaFuncSetAttribute(k_gemm_bf16<1>, cudaFuncAttributeMaxDynamicSharedMemorySize, GEMM_SMEM);
        attrs_set = true;
    }

    const int PW1 = 0, PW2 = 16384, PW3 = 49152;

    k_init<<<196, 256>>>();
    k_hist<<<(EE + 255) / 256, 256>>>(ei);
    k_wsplit_pk<<<(16384 + 255) / 256, 256>>>(W1, 128, 256, PW1);
    // launch #3 (profiled): layer-1 GEMM
    k_gemm_bf16<0><<<gemm_grid(NN, C1), 256, GEMM_SMEM>>>(x, a1s, a1d, PW1, NN, 128, C1, 4);

    k_wsplit_pk<<<(32768 + 255) / 256, 256>>>(W2, 256, 256, PW2);
    k_wsplit_pk<<<(8192 + 255) / 256, 256>>>(W3, 256, 64, PW3);
    k_wsplit_mlp<<<2, 256>>>(mlpW1);

    k_scan1<<<196, 256>>>();
    k_scan2<<<1, 256>>>();
    k_scan3<<<(NN + 255) / 256, 256>>>();
    k_scatter<<<(ETOT + 255) / 256, 256>>>(ei);

    const int aggBlocks = (NN * 32 + 255) / 256;
    const int bnApplyBlocks = (int)(((size_t)NN * C1 + 255) / 256);

    // ---- layer 1 (GEMM already issued)
    k_aggregate<4, 0><<<aggBlocks, 256>>>(b1);
    k_zero2<<<196, 256>>>();
    k_bn_stats<<<512, C1>>>();
    k_bn_finalize<<<1, C1>>>();
    k_bn_apply<<<bnApplyBlocks, 256>>>(bn1g, bn1b);

    // ---- layer 2
    k_gemm_bf16<1><<<gemm_grid(NN, C1), 256, GEMM_SMEM>>>(nullptr, a2s, a2d, PW2, NN, C1, C1, 4);
    k_aggregate<4, 0><<<aggBlocks, 256>>>(b2);
    k_zero2<<<196, 256>>>();
    k_bn_stats<<<512, C1>>>();
    k_bn_finalize<<<1, C1>>>();
    k_bn_apply<<<bnApplyBlocks, 256>>>(bn2g, bn2b);

    // ---- layer 3
    k_gemm_bf16<1><<<gemm_grid(NN, HIDV), 256, GEMM_SMEM>>>(nullptr, a3s, a3d, PW3, NN, C1, HIDV, 1);
    k_aggregate<1, 1><<<aggBlocks, 256>>>(b3);

    // ---- final scorer
    k_prep_final<<<1, 64>>>(mlpW2, mlpb2, fcW, fcb);
    k_node_scalars<<<(NN * 32 + 255) / 256, 256>>>(fcW);
    k_edge_out<<<12500, 256>>>(ei, ea, mlpb1, outp);

    (void)in_sizes; (void)n_in; (void)out_size;
}